// round 9
// baseline (speedup 1.0000x reference)
#include <cuda_runtime.h>
#include <math.h>

#define TT   4096
#define HD   512
#define NC   4880
#define G3   1536
#define SNB  128     // scan CTAs (4 outputs each, 1 per warp)

// ---------------- scratch (static device globals; no allocation) ----------------
__device__ float g_visit[(size_t)TT * HD];          // 8 MB
__device__ float g_gi[(size_t)TT * G3];             // 24 MB
__device__ float g_hs[(size_t)TT * HD];             // 8 MB; h history + delivery
__device__ unsigned g_flag[SNB];                    // per-CTA progress flags
__device__ float g_logits[TT];
__device__ float g_alpha[TT];
__device__ float g_part[64 * HD];

// ---------------- Phase 1: visit_emb = H^T @ X_emb  (4096x512, K=4880) ----------
// C[t][v] = sum_c H[c][t] * X[c][v].  128x128 tile, 8x8 per thread, kb=8.
__global__ void __launch_bounds__(256) k_visit(const float* __restrict__ H,
                                               const float* __restrict__ X) {
    __shared__ float sA[8][132];   // [k][t]
    __shared__ float sB[8][132];   // [k][v]
    const int tid = threadIdx.x;
    const int t0 = blockIdx.y << 7, v0 = blockIdx.x << 7;
    const int lk = tid >> 5;            // 0..7
    const int lc = (tid & 31) << 2;     // 0..124
    const int ty = tid >> 4;            // 0..15
    const int tx = tid & 15;

    float acc[8][8];
#pragma unroll
    for (int i = 0; i < 8; i++)
#pragma unroll
        for (int jj = 0; jj < 8; jj++) acc[i][jj] = 0.f;

    const float* pa = H + (size_t)lk * TT + t0 + lc;
    const float* pb = X + (size_t)lk * HD + v0 + lc;
    float4 an = *(const float4*)pa;
    float4 bn = *(const float4*)pb;

    for (int c0 = 0; c0 < NC; c0 += 8) {
        *(float4*)&sA[lk][lc] = an;
        *(float4*)&sB[lk][lc] = bn;
        __syncthreads();
        if (c0 + 8 < NC) {
            pa += (size_t)8 * TT;
            pb += (size_t)8 * HD;
            an = *(const float4*)pa;
            bn = *(const float4*)pb;
        }
#pragma unroll
        for (int k = 0; k < 8; k++) {
            float a[8], b[8];
            float4 a0 = *(const float4*)&sA[k][ty << 2];
            float4 a1 = *(const float4*)&sA[k][(ty << 2) + 64];
            float4 b0 = *(const float4*)&sB[k][tx << 2];
            float4 b1 = *(const float4*)&sB[k][(tx << 2) + 64];
            a[0]=a0.x; a[1]=a0.y; a[2]=a0.z; a[3]=a0.w;
            a[4]=a1.x; a[5]=a1.y; a[6]=a1.z; a[7]=a1.w;
            b[0]=b0.x; b[1]=b0.y; b[2]=b0.z; b[3]=b0.w;
            b[4]=b1.x; b[5]=b1.y; b[6]=b1.z; b[7]=b1.w;
#pragma unroll
            for (int i = 0; i < 8; i++)
#pragma unroll
                for (int jj = 0; jj < 8; jj++) acc[i][jj] += a[i] * b[jj];
        }
        __syncthreads();
    }
#pragma unroll
    for (int i = 0; i < 8; i++) {
        int row = t0 + (ty << 2) + (i & 3) + ((i >= 4) ? 64 : 0);
        float4 o0 = make_float4(acc[i][0], acc[i][1], acc[i][2], acc[i][3]);
        float4 o1 = make_float4(acc[i][4], acc[i][5], acc[i][6], acc[i][7]);
        *(float4*)&g_visit[(size_t)row * HD + v0 + (tx << 2)]      = o0;
        *(float4*)&g_visit[(size_t)row * HD + v0 + (tx << 2) + 64] = o1;
    }
}

// ---------------- Phase 2: gi = visit_emb @ W_ih^T + b_ih  (4096x1536, K=512) ---
__global__ void k_gi(const float* __restrict__ W, const float* __restrict__ bih) {
    __shared__ float sA[16][68];   // [k][t]
    __shared__ float sB[16][68];   // [k][r]
    const int tid = threadIdx.x;         // 256 threads
    const int lr = tid >> 2, lk = (tid & 3) << 2;
    const int cy = tid >> 4, cx = tid & 15;
    const int t0 = blockIdx.y << 6, r0 = blockIdx.x << 6;

    float acc[4][4];
#pragma unroll
    for (int i = 0; i < 4; i++)
#pragma unroll
        for (int j = 0; j < 4; j++) acc[i][j] = 0.f;

    for (int k0 = 0; k0 < HD; k0 += 16) {
        float4 a = *(const float4*)(g_visit + (size_t)(t0 + lr) * HD + k0 + lk);
        float4 w = *(const float4*)(W + (size_t)(r0 + lr) * HD + k0 + lk);
        sA[lk + 0][lr] = a.x; sA[lk + 1][lr] = a.y; sA[lk + 2][lr] = a.z; sA[lk + 3][lr] = a.w;
        sB[lk + 0][lr] = w.x; sB[lk + 1][lr] = w.y; sB[lk + 2][lr] = w.z; sB[lk + 3][lr] = w.w;
        __syncthreads();
#pragma unroll
        for (int k = 0; k < 16; k++) {
            float av[4], bv[4];
#pragma unroll
            for (int i = 0; i < 4; i++) av[i] = sA[k][(cy << 2) + i];
#pragma unroll
            for (int j = 0; j < 4; j++) bv[j] = sB[k][(cx << 2) + j];
#pragma unroll
            for (int i = 0; i < 4; i++)
#pragma unroll
                for (int j = 0; j < 4; j++) acc[i][j] += av[i] * bv[j];
        }
        __syncthreads();
    }
    const float4 bb = *(const float4*)&bih[r0 + (cx << 2)];
    float bv[4] = {bb.x, bb.y, bb.z, bb.w};
#pragma unroll
    for (int i = 0; i < 4; i++) {
        float4 o = make_float4(acc[i][0] + bv[0], acc[i][1] + bv[1],
                               acc[i][2] + bv[2], acc[i][3] + bv[3]);
        *(float4*)&g_gi[(size_t)(t0 + (cy << 2) + i) * G3 + r0 + (cx << 2)] = o;
    }
}

// ---------------- Phase 3: GRU scan, fence-proven protocol, flag-array barrier --
// 128 CTAs x 128 threads. Warp w of CTA b owns output j = 4b + w; W_hh rows
// {j, 512+j, 1024+j} register resident (48 floats/lane).
// Synchronization is the SAME release/acquire structure that passed in R2/R6:
//   producer: h stores -> __syncthreads -> __threadfence (release) -> flag store
//   consumer: flag poll -> __threadfence (acquire) -> __syncthreads -> __ldcg h
// The only change vs R6: ONE atomic counter (L2 serializes ~27cyc x NCTA per
// step) is replaced by per-CTA flags at DISTINCT addresses (no serialization).
__global__ void __launch_bounds__(128, 1) k_scan(const float* __restrict__ Whh,
                                                 const float* __restrict__ bhh) {
    const int b = blockIdx.x, tid = threadIdx.x;
    const int w = tid >> 5, l = tid & 31;
    const int j = (b << 2) + w;

    float wr[16], wz[16], wn[16];
    const float* Wr = Whh + (size_t)j * HD;
    const float* Wz = Whh + (size_t)(HD + j) * HD;
    const float* Wn = Whh + (size_t)(2 * HD + j) * HD;
#pragma unroll
    for (int m = 0; m < 16; m++) {
        int k = l + (m << 5);
        wr[m] = Wr[k]; wz[m] = Wz[k]; wn[m] = Wn[k];
    }
    const float br = bhh[j], bz = bhh[HD + j], bnn = bhh[2 * HD + j];

    __shared__ __align__(16) float sh[HD];
    volatile unsigned* fp = g_flag;

    for (int t = 0; t < TT; t++) {
        // prefetch input-gate values (independent of h; overlaps the wait)
        float ir = 0.f, iz = 0.f, in_ = 0.f;
        if (l == 0) {
            const float* g = g_gi + (size_t)t * G3;
            ir  = g[j];
            iz  = g[HD + j];
            in_ = g[2 * HD + j];
        }
        // wait until every CTA finished step t-1 (flag[c] >= t). Warp 0 polls
        // 4 flags per lane; flags are release-stored after h writes.
        if (w == 0 && t > 0) {
            const unsigned tgt = (unsigned)t;
            bool ok;
            do {
                unsigned f0 = fp[l];
                unsigned f1 = fp[l + 32];
                unsigned f2 = fp[l + 64];
                unsigned f3 = fp[l + 96];
                ok = (f0 >= tgt) & (f1 >= tgt) & (f2 >= tgt) & (f3 >= tgt);
            } while (!__all_sync(0xffffffffu, ok));
            __threadfence();   // acquire
        }
        __syncthreads();
        // stage h(t-1) into SMEM (one float4 per thread; L1-bypassing)
        if (t == 0)
            ((float4*)sh)[tid] = make_float4(0.f, 0.f, 0.f, 0.f);
        else
            ((float4*)sh)[tid] =
                __ldcg(((const float4*)(g_hs + (size_t)(t - 1) * HD)) + tid);
        __syncthreads();

        float ar = 0.f, az = 0.f, an = 0.f;
#pragma unroll
        for (int m = 0; m < 16; m++) {
            float hv = sh[l + (m << 5)];
            ar += wr[m] * hv;
            az += wz[m] * hv;
            an += wn[m] * hv;
        }
#pragma unroll
        for (int o = 16; o; o >>= 1) {
            ar += __shfl_down_sync(0xffffffffu, ar, o);
            az += __shfl_down_sync(0xffffffffu, az, o);
            an += __shfl_down_sync(0xffffffffu, an, o);
        }
        if (l == 0) {
            float r  = 1.f / (1.f + expf(-(ir + ar + br)));
            float z  = 1.f / (1.f + expf(-(iz + az + bz)));
            float n  = tanhf(in_ + r * (an + bnn));
            float hn = (1.f - z) * n + z * sh[j];
            g_hs[(size_t)t * HD + j] = hn;
        }
        __syncthreads();              // all 4 h stores of this CTA done
        if (tid == 0) {
            __threadfence();          // release h stores
            fp[b] = (unsigned)(t + 1);
        }
    }
}

// ---------------- Phase 4: attention pooling ------------------------------------
__global__ void k_logits(const float* __restrict__ watt) {
    const int wp = threadIdx.x >> 5, l = threadIdx.x & 31;
    const int t = (blockIdx.x << 3) + wp;
    const float* hr = g_hs + (size_t)t * HD;
    float s = 0.f;
#pragma unroll
    for (int m = 0; m < 16; m++) {
        int k = l + (m << 5);
        s += hr[k] * watt[k];
    }
#pragma unroll
    for (int o = 16; o; o >>= 1) s += __shfl_down_sync(0xffffffffu, s, o);
    if (l == 0) g_logits[t] = s;
}

__global__ void k_softmax() {
    __shared__ float sred[16];
    const int tid = threadIdx.x;   // 512 threads, 8 logits each
    float v[8];
    float mx = -3.402823466e38f;
#pragma unroll
    for (int i = 0; i < 8; i++) {
        v[i] = g_logits[tid + (i << 9)];
        mx = fmaxf(mx, v[i]);
    }
#pragma unroll
    for (int o = 16; o; o >>= 1) mx = fmaxf(mx, __shfl_xor_sync(0xffffffffu, mx, o));
    if ((tid & 31) == 0) sred[tid >> 5] = mx;
    __syncthreads();
    if (tid == 0) {
        float m = sred[0];
        for (int i = 1; i < 16; i++) m = fmaxf(m, sred[i]);
        sred[0] = m;
    }
    __syncthreads();
    const float m = sred[0];
    __syncthreads();
    float s = 0.f;
#pragma unroll
    for (int i = 0; i < 8; i++) {
        v[i] = expf(v[i] - m);
        s += v[i];
    }
#pragma unroll
    for (int o = 16; o; o >>= 1) s += __shfl_xor_sync(0xffffffffu, s, o);
    if ((tid & 31) == 0) sred[tid >> 5] = s;
    __syncthreads();
    if (tid == 0) {
        float S = 0.f;
        for (int i = 0; i < 16; i++) S += sred[i];
        sred[0] = S;
    }
    __syncthreads();
    const float inv = 1.f / sred[0];
#pragma unroll
    for (int i = 0; i < 8; i++) g_alpha[tid + (i << 9)] = v[i] * inv;
}

__global__ void k_wsum() {
    const int j = threadIdx.x, b = blockIdx.x;   // 64 blocks x 512 threads
    float acc = 0.f;
    const int t0 = b << 6;
    for (int t = t0; t < t0 + 64; t++)
        acc += g_alpha[t] * g_hs[(size_t)t * HD + j];
    g_part[b * HD + j] = acc;
}

__global__ void k_final(float* __restrict__ out) {
    const int j = threadIdx.x;
    float a = 0.f;
    for (int b = 0; b < 64; b++) a += g_part[b * HD + j];
    out[j] = a;
}

// ---------------- launch --------------------------------------------------------
extern "C" void kernel_launch(void* const* d_in, const int* in_sizes, int n_in,
                              void* d_out, int out_size) {
    const float* H    = (const float*)d_in[0];
    // d_in[1] = TE (unused by reference)
    const float* X    = (const float*)d_in[2];
    const float* Wih  = (const float*)d_in[3];
    const float* Whh  = (const float*)d_in[4];
    const float* bih  = (const float*)d_in[5];
    const float* bhh  = (const float*)d_in[6];
    const float* watt = (const float*)d_in[7];
    float* out = (float*)d_out;

    void* pflag = 0;
    cudaGetSymbolAddress(&pflag, g_flag);
    cudaMemsetAsync(pflag, 0, SNB * sizeof(unsigned));  // reset flags each launch

    k_visit<<<dim3(HD / 128, TT / 128), 256>>>(H, X);
    k_gi<<<dim3(G3 / 64, TT / 64), 256>>>(Wih, bih);
    k_scan<<<SNB, 128>>>(Whh, bhh);
    k_logits<<<TT / 8, 256>>>(watt);
    k_softmax<<<1, 512>>>();
    k_wsum<<<64, 512>>>();
    k_final<<<1, 512>>>(out);
}

// round 10
// speedup vs baseline: 1.5080x; 1.5080x over previous
#include <cuda_runtime.h>
#include <math.h>
#include <stdint.h>

#define TT   4096
#define HD   512
#define NC   4880
#define G3   1536
#define CLN  16      // scan cluster size = grid size (all-to-all DSMEM)

// ---------------- scratch (static device globals; no allocation) ----------------
__device__ float g_visit[(size_t)TT * HD];          // 8 MB
__device__ float g_gi[(size_t)TT * G3];             // 24 MB
__device__ float g_hs[(size_t)TT * HD];             // 8 MB
__device__ float g_logits[TT];
__device__ float g_alpha[TT];
__device__ float g_part[64 * HD];

// ---------------- Phase 1: visit_emb = H^T @ X_emb  (4096x512, K=4880) ----------
__global__ void __launch_bounds__(256) k_visit(const float* __restrict__ H,
                                               const float* __restrict__ X) {
    __shared__ float sA[8][132];   // [k][t]
    __shared__ float sB[8][132];   // [k][v]
    const int tid = threadIdx.x;
    const int t0 = blockIdx.y << 7, v0 = blockIdx.x << 7;
    const int lk = tid >> 5;            // 0..7
    const int lc = (tid & 31) << 2;     // 0..124
    const int ty = tid >> 4;            // 0..15
    const int tx = tid & 15;

    float acc[8][8];
#pragma unroll
    for (int i = 0; i < 8; i++)
#pragma unroll
        for (int jj = 0; jj < 8; jj++) acc[i][jj] = 0.f;

    const float* pa = H + (size_t)lk * TT + t0 + lc;
    const float* pb = X + (size_t)lk * HD + v0 + lc;
    float4 an = *(const float4*)pa;
    float4 bn = *(const float4*)pb;

    for (int c0 = 0; c0 < NC; c0 += 8) {
        *(float4*)&sA[lk][lc] = an;
        *(float4*)&sB[lk][lc] = bn;
        __syncthreads();
        if (c0 + 8 < NC) {
            pa += (size_t)8 * TT;
            pb += (size_t)8 * HD;
            an = *(const float4*)pa;
            bn = *(const float4*)pb;
        }
#pragma unroll
        for (int k = 0; k < 8; k++) {
            float a[8], b[8];
            float4 a0 = *(const float4*)&sA[k][ty << 2];
            float4 a1 = *(const float4*)&sA[k][(ty << 2) + 64];
            float4 b0 = *(const float4*)&sB[k][tx << 2];
            float4 b1 = *(const float4*)&sB[k][(tx << 2) + 64];
            a[0]=a0.x; a[1]=a0.y; a[2]=a0.z; a[3]=a0.w;
            a[4]=a1.x; a[5]=a1.y; a[6]=a1.z; a[7]=a1.w;
            b[0]=b0.x; b[1]=b0.y; b[2]=b0.z; b[3]=b0.w;
            b[4]=b1.x; b[5]=b1.y; b[6]=b1.z; b[7]=b1.w;
#pragma unroll
            for (int i = 0; i < 8; i++)
#pragma unroll
                for (int jj = 0; jj < 8; jj++) acc[i][jj] += a[i] * b[jj];
        }
        __syncthreads();
    }
#pragma unroll
    for (int i = 0; i < 8; i++) {
        int row = t0 + (ty << 2) + (i & 3) + ((i >= 4) ? 64 : 0);
        float4 o0 = make_float4(acc[i][0], acc[i][1], acc[i][2], acc[i][3]);
        float4 o1 = make_float4(acc[i][4], acc[i][5], acc[i][6], acc[i][7]);
        *(float4*)&g_visit[(size_t)row * HD + v0 + (tx << 2)]      = o0;
        *(float4*)&g_visit[(size_t)row * HD + v0 + (tx << 2) + 64] = o1;
    }
}

// ---------------- Phase 2: gi = visit_emb @ W_ih^T + b_ih  (4096x1536, K=512) ---
__global__ void k_gi(const float* __restrict__ W, const float* __restrict__ bih) {
    __shared__ float sA[16][68];   // [k][t]
    __shared__ float sB[16][68];   // [k][r]
    const int tid = threadIdx.x;         // 256 threads
    const int lr = tid >> 2, lk = (tid & 3) << 2;
    const int cy = tid >> 4, cx = tid & 15;
    const int t0 = blockIdx.y << 6, r0 = blockIdx.x << 6;

    float acc[4][4];
#pragma unroll
    for (int i = 0; i < 4; i++)
#pragma unroll
        for (int j = 0; j < 4; j++) acc[i][j] = 0.f;

    for (int k0 = 0; k0 < HD; k0 += 16) {
        float4 a = *(const float4*)(g_visit + (size_t)(t0 + lr) * HD + k0 + lk);
        float4 w = *(const float4*)(W + (size_t)(r0 + lr) * HD + k0 + lk);
        sA[lk + 0][lr] = a.x; sA[lk + 1][lr] = a.y; sA[lk + 2][lr] = a.z; sA[lk + 3][lr] = a.w;
        sB[lk + 0][lr] = w.x; sB[lk + 1][lr] = w.y; sB[lk + 2][lr] = w.z; sB[lk + 3][lr] = w.w;
        __syncthreads();
#pragma unroll
        for (int k = 0; k < 16; k++) {
            float av[4], bv[4];
#pragma unroll
            for (int i = 0; i < 4; i++) av[i] = sA[k][(cy << 2) + i];
#pragma unroll
            for (int j = 0; j < 4; j++) bv[j] = sB[k][(cx << 2) + j];
#pragma unroll
            for (int i = 0; i < 4; i++)
#pragma unroll
                for (int j = 0; j < 4; j++) acc[i][j] += av[i] * bv[j];
        }
        __syncthreads();
    }
    const float4 bb = *(const float4*)&bih[r0 + (cx << 2)];
    float bv[4] = {bb.x, bb.y, bb.z, bb.w};
#pragma unroll
    for (int i = 0; i < 4; i++) {
        float4 o = make_float4(acc[i][0] + bv[0], acc[i][1] + bv[1],
                               acc[i][2] + bv[2], acc[i][3] + bv[3]);
        *(float4*)&g_gi[(size_t)(t0 + (cy << 2) + i) * G3 + r0 + (cx << 2)] = o;
    }
}

// ---------------- Phase 3: GRU scan — one 16-CTA cluster, DSMEM h exchange ------
// Grid = cluster = 16 CTAs x 512 threads. CTA b owns outputs j in [32b, 32b+32).
// Gate rows of CTA b: i = g*32 + o  ->  W_hh row g*512 + 32b + o  (g: 0=r,1=z,2=n).
// Warp w handles rows i = 6w .. 6w+5; lane l holds cols k = l + 32m (96 regs).
// Per step: matvec from local sh[cur] -> shfl reduce -> sdot -> warp0 gates ->
// broadcast 32 h values to EVERY cluster rank's sh[nxt] via mapa+st.shared::cluster
// (warp r targets rank r, one store per lane) -> barrier.cluster (arrive=release
// orders the DSMEM stores, wait=acquire makes them visible — the proven pattern).
// WAR safety: double-buffered sh; reads of sh[cur] at step t precede the arrive,
// and any write to sh[cur] (step t+1) follows the wait, so one sync/step suffices.
__global__ void __launch_bounds__(512, 1) __cluster_dims__(CLN, 1, 1)
k_scan(const float* __restrict__ Whh, const float* __restrict__ bhh) {
    const int b = blockIdx.x, tid = threadIdx.x;
    const int w = tid >> 5, l = tid & 31;

    // register-resident weights: wv[r*16+m] = Whh[row(6w+r)][l+32m]
    float wv[96];
#pragma unroll
    for (int r = 0; r < 6; r++) {
        const int i = 6 * w + r;
        const size_t row = (size_t)(i >> 5) * HD + (b << 5) + (i & 31);
#pragma unroll
        for (int m = 0; m < 16; m++)
            wv[r * 16 + m] = Whh[row * HD + l + (m << 5)];
    }

    __shared__ float sh[2][HD];    // h double buffer (all 512 values, every CTA)
    __shared__ float sdot[96];     // per-row dot results
    __shared__ float stg[32];      // this CTA's new h values
    __shared__ float sbias[96];    // bhh for this CTA's rows

    if (tid < 96)
        sbias[tid] = bhh[(size_t)(tid >> 5) * HD + (b << 5) + (tid & 31)];
    for (int i = tid; i < HD; i += 512) sh[0][i] = 0.f;   // h(-1) = 0
    __syncthreads();

    for (int t = 0; t < TT; t++) {
        const int cur = t & 1;
        const float* S = sh[cur];

        // prefetch input-gate values (independent of h)
        float ir = 0.f, iz = 0.f, in_ = 0.f;
        if (tid < 32) {
            const float* g = g_gi + (size_t)t * G3 + (b << 5) + tid;
            ir  = g[0];
            iz  = g[HD];
            in_ = g[2 * HD];
        }

        float a0 = 0.f, a1 = 0.f, a2 = 0.f, a3 = 0.f, a4 = 0.f, a5 = 0.f;
#pragma unroll
        for (int m = 0; m < 16; m++) {
            const float hv = S[l + (m << 5)];
            a0 += wv[m]      * hv;
            a1 += wv[16 + m] * hv;
            a2 += wv[32 + m] * hv;
            a3 += wv[48 + m] * hv;
            a4 += wv[64 + m] * hv;
            a5 += wv[80 + m] * hv;
        }
#pragma unroll
        for (int o = 16; o; o >>= 1) {
            a0 += __shfl_down_sync(0xffffffffu, a0, o);
            a1 += __shfl_down_sync(0xffffffffu, a1, o);
            a2 += __shfl_down_sync(0xffffffffu, a2, o);
            a3 += __shfl_down_sync(0xffffffffu, a3, o);
            a4 += __shfl_down_sync(0xffffffffu, a4, o);
            a5 += __shfl_down_sync(0xffffffffu, a5, o);
        }
        if (l == 0) {
            const int i0 = 6 * w;
            sdot[i0 + 0] = a0; sdot[i0 + 1] = a1; sdot[i0 + 2] = a2;
            sdot[i0 + 3] = a3; sdot[i0 + 4] = a4; sdot[i0 + 5] = a5;
        }
        __syncthreads();

        if (tid < 32) {
            const float ar = sdot[tid], az = sdot[32 + tid], an = sdot[64 + tid];
            const float r  = 1.f / (1.f + expf(-(ir + ar + sbias[tid])));
            const float z  = 1.f / (1.f + expf(-(iz + az + sbias[32 + tid])));
            const float n  = tanhf(in_ + r * (an + sbias[64 + tid]));
            const float hn = (1.f - z) * n + z * S[(b << 5) + tid];
            stg[tid] = hn;
            g_hs[(size_t)t * HD + (b << 5) + tid] = hn;
        }
        __syncthreads();

        // broadcast: warp w delivers this CTA's 32 values into rank w's sh[nxt]
        {
            const float v = stg[l];
            uint32_t laddr =
                (uint32_t)__cvta_generic_to_shared(&sh[cur ^ 1][(b << 5) + l]);
            asm volatile(
                "{\n\t"
                ".reg .b32 ra;\n\t"
                "mapa.shared::cluster.u32 ra, %0, %1;\n\t"
                "st.shared::cluster.f32 [ra], %2;\n\t"
                "}"
                :: "r"(laddr), "r"(w), "f"(v) : "memory");
        }
        asm volatile("barrier.cluster.arrive.aligned;" ::: "memory");
        asm volatile("barrier.cluster.wait.aligned;" ::: "memory");
    }
}

// ---------------- Phase 4: attention pooling ------------------------------------
__global__ void k_logits(const float* __restrict__ watt) {
    const int wp = threadIdx.x >> 5, l = threadIdx.x & 31;
    const int t = (blockIdx.x << 3) + wp;
    const float* hr = g_hs + (size_t)t * HD;
    float s = 0.f;
#pragma unroll
    for (int m = 0; m < 16; m++) {
        int k = l + (m << 5);
        s += hr[k] * watt[k];
    }
#pragma unroll
    for (int o = 16; o; o >>= 1) s += __shfl_down_sync(0xffffffffu, s, o);
    if (l == 0) g_logits[t] = s;
}

__global__ void k_softmax() {
    __shared__ float sred[16];
    const int tid = threadIdx.x;   // 512 threads, 8 logits each
    float v[8];
    float mx = -3.402823466e38f;
#pragma unroll
    for (int i = 0; i < 8; i++) {
        v[i] = g_logits[tid + (i << 9)];
        mx = fmaxf(mx, v[i]);
    }
#pragma unroll
    for (int o = 16; o; o >>= 1) mx = fmaxf(mx, __shfl_xor_sync(0xffffffffu, mx, o));
    if ((tid & 31) == 0) sred[tid >> 5] = mx;
    __syncthreads();
    if (tid == 0) {
        float m = sred[0];
        for (int i = 1; i < 16; i++) m = fmaxf(m, sred[i]);
        sred[0] = m;
    }
    __syncthreads();
    const float m = sred[0];
    __syncthreads();
    float s = 0.f;
#pragma unroll
    for (int i = 0; i < 8; i++) {
        v[i] = expf(v[i] - m);
        s += v[i];
    }
#pragma unroll
    for (int o = 16; o; o >>= 1) s += __shfl_xor_sync(0xffffffffu, s, o);
    if ((tid & 31) == 0) sred[tid >> 5] = s;
    __syncthreads();
    if (tid == 0) {
        float S = 0.f;
        for (int i = 0; i < 16; i++) S += sred[i];
        sred[0] = S;
    }
    __syncthreads();
    const float inv = 1.f / sred[0];
#pragma unroll
    for (int i = 0; i < 8; i++) g_alpha[tid + (i << 9)] = v[i] * inv;
}

__global__ void k_wsum() {
    const int j = threadIdx.x, b = blockIdx.x;   // 64 blocks x 512 threads
    float acc = 0.f;
    const int t0 = b << 6;
    for (int t = t0; t < t0 + 64; t++)
        acc += g_alpha[t] * g_hs[(size_t)t * HD + j];
    g_part[b * HD + j] = acc;
}

__global__ void k_final(float* __restrict__ out) {
    const int j = threadIdx.x;
    float a = 0.f;
    for (int b = 0; b < 64; b++) a += g_part[b * HD + j];
    out[j] = a;
}

// ---------------- launch --------------------------------------------------------
extern "C" void kernel_launch(void* const* d_in, const int* in_sizes, int n_in,
                              void* d_out, int out_size) {
    const float* H    = (const float*)d_in[0];
    // d_in[1] = TE (unused by reference)
    const float* X    = (const float*)d_in[2];
    const float* Wih  = (const float*)d_in[3];
    const float* Whh  = (const float*)d_in[4];
    const float* bih  = (const float*)d_in[5];
    const float* bhh  = (const float*)d_in[6];
    const float* watt = (const float*)d_in[7];
    float* out = (float*)d_out;

    // cluster size 16 > portable max 8: opt in (host-side attr, idempotent,
    // not a stream op — safe under graph capture)
    cudaFuncSetAttribute((const void*)k_scan,
                         cudaFuncAttributeNonPortableClusterSizeAllowed, 1);

    k_visit<<<dim3(HD / 128, TT / 128), 256>>>(H, X);
    k_gi<<<dim3(G3 / 64, TT / 64), 256>>>(Wih, bih);
    k_scan<<<CLN, 512>>>(Whh, bhh);       // cluster dims from __cluster_dims__
    k_logits<<<TT / 8, 256>>>(watt);
    k_softmax<<<1, 512>>>();
    k_wsum<<<64, 512>>>();
    k_final<<<1, 512>>>(out);
}

// round 11
// speedup vs baseline: 2.1205x; 1.4062x over previous
#include <cuda_runtime.h>
#include <math.h>
#include <stdint.h>

#define TT   4096
#define HD   512
#define NC   4880
#define G3   1536
#define CLN  16      // scan cluster size = grid size (all-to-all DSMEM)

// ---------------- scratch (static device globals; no allocation) ----------------
__device__ float g_visit[(size_t)TT * HD];          // 8 MB
__device__ float g_gi[(size_t)TT * G3];             // 24 MB
__device__ float g_hs[(size_t)TT * HD];             // 8 MB
__device__ float g_logits[TT];
__device__ float g_alpha[TT];
__device__ float g_part[64 * HD];

// ---------------- f32x2 helpers (SASS FFMA2 — PTX-only, ptxas never fuses) ------
__device__ __forceinline__ unsigned long long pk2(float x, float y) {
    unsigned long long r;
    asm("mov.b64 %0, {%1, %2};" : "=l"(r) : "f"(x), "f"(y));
    return r;
}
__device__ __forceinline__ void upk2(unsigned long long p, float& x, float& y) {
    asm("mov.b64 {%0, %1}, %2;" : "=f"(x), "=f"(y) : "l"(p));
}
__device__ __forceinline__ void fma2(unsigned long long& d,
                                     unsigned long long a, unsigned long long b) {
    asm("fma.rn.f32x2 %0, %1, %2, %3;" : "=l"(d) : "l"(a), "l"(b), "l"(d));
}

// ---------------- Phase 1: visit_emb = H^T @ X_emb  (4096x512, K=4880) ----------
// 128x128 tile, 8x8 per thread, kb=8, f32x2 accumulation (each scalar chain is
// bitwise identical to the scalar version: pairs pack the j dimension).
__global__ void __launch_bounds__(256) k_visit(const float* __restrict__ H,
                                               const float* __restrict__ X) {
    __shared__ float sA[8][132];   // [k][t]
    __shared__ float sB[8][132];   // [k][v]
    const int tid = threadIdx.x;
    const int t0 = blockIdx.y << 7, v0 = blockIdx.x << 7;
    const int lk = tid >> 5;            // 0..7
    const int lc = (tid & 31) << 2;     // 0..124
    const int ty = tid >> 4;            // 0..15
    const int tx = tid & 15;

    unsigned long long acc2[8][4];
#pragma unroll
    for (int i = 0; i < 8; i++)
#pragma unroll
        for (int jj = 0; jj < 4; jj++) acc2[i][jj] = pk2(0.f, 0.f);

    const float* pa = H + (size_t)lk * TT + t0 + lc;
    const float* pb = X + (size_t)lk * HD + v0 + lc;
    float4 an = *(const float4*)pa;
    float4 bn = *(const float4*)pb;

    for (int c0 = 0; c0 < NC; c0 += 8) {
        *(float4*)&sA[lk][lc] = an;
        *(float4*)&sB[lk][lc] = bn;
        __syncthreads();
        if (c0 + 8 < NC) {
            pa += (size_t)8 * TT;
            pb += (size_t)8 * HD;
            an = *(const float4*)pa;
            bn = *(const float4*)pb;
        }
#pragma unroll
        for (int k = 0; k < 8; k++) {
            float a[8];
            float4 a0 = *(const float4*)&sA[k][ty << 2];
            float4 a1 = *(const float4*)&sA[k][(ty << 2) + 64];
            float4 b0 = *(const float4*)&sB[k][tx << 2];
            float4 b1 = *(const float4*)&sB[k][(tx << 2) + 64];
            a[0]=a0.x; a[1]=a0.y; a[2]=a0.z; a[3]=a0.w;
            a[4]=a1.x; a[5]=a1.y; a[6]=a1.z; a[7]=a1.w;
            unsigned long long bb[4];
            bb[0] = pk2(b0.x, b0.y); bb[1] = pk2(b0.z, b0.w);
            bb[2] = pk2(b1.x, b1.y); bb[3] = pk2(b1.z, b1.w);
#pragma unroll
            for (int i = 0; i < 8; i++) {
                const unsigned long long aa = pk2(a[i], a[i]);
#pragma unroll
                for (int jj = 0; jj < 4; jj++) fma2(acc2[i][jj], aa, bb[jj]);
            }
        }
        __syncthreads();
    }
#pragma unroll
    for (int i = 0; i < 8; i++) {
        int row = t0 + (ty << 2) + (i & 3) + ((i >= 4) ? 64 : 0);
        float4 o0, o1;
        upk2(acc2[i][0], o0.x, o0.y); upk2(acc2[i][1], o0.z, o0.w);
        upk2(acc2[i][2], o1.x, o1.y); upk2(acc2[i][3], o1.z, o1.w);
        *(float4*)&g_visit[(size_t)row * HD + v0 + (tx << 2)]      = o0;
        *(float4*)&g_visit[(size_t)row * HD + v0 + (tx << 2) + 64] = o1;
    }
}

// ---------------- Phase 2: gi = visit_emb @ W_ih^T + b_ih  (4096x1536, K=512) ---
// 128x128 tile, 8x8 per thread, kb=8, f32x2; K-contiguous inputs transposed on
// the SMEM store (4 scalar STS per float4, conflict-free).
__global__ void __launch_bounds__(256) k_gi(const float* __restrict__ W,
                                            const float* __restrict__ bih) {
    __shared__ float sA[8][132];   // [k][t]
    __shared__ float sB[8][132];   // [k][r]
    const int tid = threadIdx.x;
    const int t0 = blockIdx.y << 7, r0 = blockIdx.x << 7;
    const int lr = tid >> 1;            // 0..127 (row within tile)
    const int lk = (tid & 1) << 2;      // 0 or 4
    const int ty = tid >> 4;            // 0..15
    const int tx = tid & 15;

    unsigned long long acc2[8][4];
#pragma unroll
    for (int i = 0; i < 8; i++)
#pragma unroll
        for (int jj = 0; jj < 4; jj++) acc2[i][jj] = pk2(0.f, 0.f);

    const float* pa = g_visit + (size_t)(t0 + lr) * HD + lk;
    const float* pb = W + (size_t)(r0 + lr) * HD + lk;
    float4 an = *(const float4*)pa;
    float4 bn = *(const float4*)pb;

    for (int k0 = 0; k0 < HD; k0 += 8) {
        sA[lk + 0][lr] = an.x; sA[lk + 1][lr] = an.y;
        sA[lk + 2][lr] = an.z; sA[lk + 3][lr] = an.w;
        sB[lk + 0][lr] = bn.x; sB[lk + 1][lr] = bn.y;
        sB[lk + 2][lr] = bn.z; sB[lk + 3][lr] = bn.w;
        __syncthreads();
        if (k0 + 8 < HD) {
            pa += 8;
            pb += 8;
            an = *(const float4*)pa;
            bn = *(const float4*)pb;
        }
#pragma unroll
        for (int k = 0; k < 8; k++) {
            float a[8];
            float4 a0 = *(const float4*)&sA[k][ty << 2];
            float4 a1 = *(const float4*)&sA[k][(ty << 2) + 64];
            float4 b0 = *(const float4*)&sB[k][tx << 2];
            float4 b1 = *(const float4*)&sB[k][(tx << 2) + 64];
            a[0]=a0.x; a[1]=a0.y; a[2]=a0.z; a[3]=a0.w;
            a[4]=a1.x; a[5]=a1.y; a[6]=a1.z; a[7]=a1.w;
            unsigned long long bb[4];
            bb[0] = pk2(b0.x, b0.y); bb[1] = pk2(b0.z, b0.w);
            bb[2] = pk2(b1.x, b1.y); bb[3] = pk2(b1.z, b1.w);
#pragma unroll
            for (int i = 0; i < 8; i++) {
                const unsigned long long aa = pk2(a[i], a[i]);
#pragma unroll
                for (int jj = 0; jj < 4; jj++) fma2(acc2[i][jj], aa, bb[jj]);
            }
        }
        __syncthreads();
    }
    const float4 bb0 = *(const float4*)&bih[r0 + (tx << 2)];
    const float4 bb1 = *(const float4*)&bih[r0 + (tx << 2) + 64];
#pragma unroll
    for (int i = 0; i < 8; i++) {
        int row = t0 + (ty << 2) + (i & 3) + ((i >= 4) ? 64 : 0);
        float4 o0, o1;
        upk2(acc2[i][0], o0.x, o0.y); upk2(acc2[i][1], o0.z, o0.w);
        upk2(acc2[i][2], o1.x, o1.y); upk2(acc2[i][3], o1.z, o1.w);
        o0.x += bb0.x; o0.y += bb0.y; o0.z += bb0.z; o0.w += bb0.w;
        o1.x += bb1.x; o1.y += bb1.y; o1.z += bb1.z; o1.w += bb1.w;
        *(float4*)&g_gi[(size_t)row * G3 + r0 + (tx << 2)]      = o0;
        *(float4*)&g_gi[(size_t)row * G3 + r0 + (tx << 2) + 64] = o1;
    }
}

// ---------------- Phase 3: GRU scan — cluster-16, per-output warps, FFMA2 -------
// Grid = cluster = 16 CTAs x 512 threads (16 warps). Warp w of CTA b owns
// outputs j0=32b+2w and j0+1 — ALL THREE gate rows of both (6 rows). Lane l
// holds column pairs {64m+2l, 64m+2l+1}, m=0..7: 48 f32x2 weight regs (=96 f32,
// same pressure as R10). Per step: 48 FFMA2 matvec -> 5-level xor reduce (sums
// on every lane) -> every lane computes the full gate chain for output (l&1)
// (parallel, no sdot exchange, no extra syncthreads) -> lane l stores its h to
// rank l>>1 via mapa + st.shared::cluster -> barrier.cluster (R10-proven:
// arrive releases the DSMEM stores, wait acquires them). Double-buffered sh:
// reads of sh[cur] precede the arrive; any peer write to sh[cur] (their step
// t+1) follows their wait, which requires our arrive. Same safety as R10.
__global__ void __launch_bounds__(512, 1) __cluster_dims__(CLN, 1, 1)
k_scan(const float* __restrict__ Whh, const float* __restrict__ bhh) {
    const int b = blockIdx.x, tid = threadIdx.x;
    const int w = tid >> 5, l = tid & 31;
    const int j0 = (b << 5) + (w << 1);     // first of this warp's two outputs
    const int jo = j0 + (l & 1);            // the output THIS lane gates

    // weights: wv2[rr*8+m] = {Whh[row][64m+2l], Whh[row][64m+2l+1]},
    // rr = gate*2 + out  (gate 0=r,1=z,2=n; out 0/1)
    unsigned long long wv2[48];
#pragma unroll
    for (int rr = 0; rr < 6; rr++) {
        const size_t row = (size_t)(rr >> 1) * HD + j0 + (rr & 1);
#pragma unroll
        for (int m = 0; m < 8; m++) {
            const float2 v = *(const float2*)(Whh + row * HD + (m << 6) + (l << 1));
            wv2[rr * 8 + m] = pk2(v.x, v.y);
        }
    }
    // per-lane biases for output jo
    const float br  = bhh[jo];
    const float bz  = bhh[HD + jo];
    const float bnn = bhh[2 * HD + jo];

    __shared__ __align__(16) float sh[2][HD];   // h double buffer
    for (int i = tid; i < HD; i += 512) sh[0][i] = 0.f;   // h(-1) = 0
    __syncthreads();

    for (int t = 0; t < TT; t++) {
        const int cur = t & 1;
        const float* S = sh[cur];

        // prefetch input-gate values for output jo (independent of h)
        float ir = 0.f, iz = 0.f, in_ = 0.f;
        if (l < 2) {
            const float* g = g_gi + (size_t)t * G3 + jo;
            ir  = g[0];
            iz  = g[HD];
            in_ = g[2 * HD];
        }

        // matvec: 6 packed accumulators over 8 column-pair groups
        unsigned long long A2[6];
#pragma unroll
        for (int rr = 0; rr < 6; rr++) A2[rr] = pk2(0.f, 0.f);
        const unsigned long long* S2 = (const unsigned long long*)S;
#pragma unroll
        for (int m = 0; m < 8; m++) {
            const unsigned long long hv = S2[(m << 5) + l];
#pragma unroll
            for (int rr = 0; rr < 6; rr++) fma2(A2[rr], wv2[rr * 8 + m], hv);
        }
        float A[6];
#pragma unroll
        for (int rr = 0; rr < 6; rr++) {
            float x, y;
            upk2(A2[rr], x, y);
            A[rr] = x + y;
        }
#pragma unroll
        for (int o = 16; o; o >>= 1)
#pragma unroll
            for (int rr = 0; rr < 6; rr++)
                A[rr] += __shfl_xor_sync(0xffffffffu, A[rr], o);

        // gates: broadcast gi from lanes 0/1, then every lane computes its output
        ir  = __shfl_sync(0xffffffffu, ir,  l & 1);
        iz  = __shfl_sync(0xffffffffu, iz,  l & 1);
        in_ = __shfl_sync(0xffffffffu, in_, l & 1);
        const float ar = A[0 + (l & 1)];
        const float az = A[2 + (l & 1)];
        const float an = A[4 + (l & 1)];
        const float r  = 1.f / (1.f + expf(-(ir + ar + br)));
        const float z  = 1.f / (1.f + expf(-(iz + az + bz)));
        const float n  = tanhf(in_ + r * (an + bnn));
        const float hn = (1.f - z) * n + z * S[jo];

        if (l < 2) g_hs[(size_t)t * HD + jo] = hn;

        // broadcast: lane l delivers output jo's value into rank (l>>1)'s sh[nxt]
        {
            uint32_t laddr =
                (uint32_t)__cvta_generic_to_shared(&sh[cur ^ 1][jo]);
            asm volatile(
                "{\n\t"
                ".reg .b32 ra;\n\t"
                "mapa.shared::cluster.u32 ra, %0, %1;\n\t"
                "st.shared::cluster.f32 [ra], %2;\n\t"
                "}"
                :: "r"(laddr), "r"(l >> 1), "f"(hn) : "memory");
        }
        asm volatile("barrier.cluster.arrive.aligned;" ::: "memory");
        asm volatile("barrier.cluster.wait.aligned;" ::: "memory");
    }
}

// ---------------- Phase 4: attention pooling ------------------------------------
__global__ void k_logits(const float* __restrict__ watt) {
    const int wp = threadIdx.x >> 5, l = threadIdx.x & 31;
    const int t = (blockIdx.x << 3) + wp;
    const float* hr = g_hs + (size_t)t * HD;
    float s = 0.f;
#pragma unroll
    for (int m = 0; m < 16; m++) {
        int k = l + (m << 5);
        s += hr[k] * watt[k];
    }
#pragma unroll
    for (int o = 16; o; o >>= 1) s += __shfl_down_sync(0xffffffffu, s, o);
    if (l == 0) g_logits[t] = s;
}

__global__ void k_softmax() {
    __shared__ float sred[16];
    const int tid = threadIdx.x;   // 512 threads, 8 logits each
    float v[8];
    float mx = -3.402823466e38f;
#pragma unroll
    for (int i = 0; i < 8; i++) {
        v[i] = g_logits[tid + (i << 9)];
        mx = fmaxf(mx, v[i]);
    }
#pragma unroll
    for (int o = 16; o; o >>= 1) mx = fmaxf(mx, __shfl_xor_sync(0xffffffffu, mx, o));
    if ((tid & 31) == 0) sred[tid >> 5] = mx;
    __syncthreads();
    if (tid == 0) {
        float m = sred[0];
        for (int i = 1; i < 16; i++) m = fmaxf(m, sred[i]);
        sred[0] = m;
    }
    __syncthreads();
    const float m = sred[0];
    __syncthreads();
    float s = 0.f;
#pragma unroll
    for (int i = 0; i < 8; i++) {
        v[i] = expf(v[i] - m);
        s += v[i];
    }
#pragma unroll
    for (int o = 16; o; o >>= 1) s += __shfl_xor_sync(0xffffffffu, s, o);
    if ((tid & 31) == 0) sred[tid >> 5] = s;
    __syncthreads();
    if (tid == 0) {
        float S = 0.f;
        for (int i = 0; i < 16; i++) S += sred[i];
        sred[0] = S;
    }
    __syncthreads();
    const float inv = 1.f / sred[0];
#pragma unroll
    for (int i = 0; i < 8; i++) g_alpha[tid + (i << 9)] = v[i] * inv;
}

__global__ void k_wsum() {
    const int j = threadIdx.x, b = blockIdx.x;   // 64 blocks x 512 threads
    float acc = 0.f;
    const int t0 = b << 6;
    for (int t = t0; t < t0 + 64; t++)
        acc += g_alpha[t] * g_hs[(size_t)t * HD + j];
    g_part[b * HD + j] = acc;
}

__global__ void k_final(float* __restrict__ out) {
    const int j = threadIdx.x;
    float a = 0.f;
    for (int b = 0; b < 64; b++) a += g_part[b * HD + j];
    out[j] = a;
}

// ---------------- launch --------------------------------------------------------
extern "C" void kernel_launch(void* const* d_in, const int* in_sizes, int n_in,
                              void* d_out, int out_size) {
    const float* H    = (const float*)d_in[0];
    // d_in[1] = TE (unused by reference)
    const float* X    = (const float*)d_in[2];
    const float* Wih  = (const float*)d_in[3];
    const float* Whh  = (const float*)d_in[4];
    const float* bih  = (const float*)d_in[5];
    const float* bhh  = (const float*)d_in[6];
    const float* watt = (const float*)d_in[7];
    float* out = (float*)d_out;

    // cluster size 16 > portable max 8: opt in (host attr, graph-capture safe)
    cudaFuncSetAttribute((const void*)k_scan,
                         cudaFuncAttributeNonPortableClusterSizeAllowed, 1);

    k_visit<<<dim3(HD / 128, TT / 128), 256>>>(H, X);
    k_gi<<<dim3(G3 / 128, TT / 128), 256>>>(Wih, bih);
    k_scan<<<CLN, 512>>>(Whh, bhh);       // cluster dims from __cluster_dims__
    k_logits<<<TT / 8, 256>>>(watt);
    k_softmax<<<1, 512>>>();
    k_wsum<<<64, 512>>>();
    k_final<<<1, 512>>>(out);
}

// round 12
// speedup vs baseline: 2.3932x; 1.1286x over previous
#include <cuda_runtime.h>
#include <math.h>
#include <stdint.h>

#define TT   4096
#define HD   512
#define NC   4880
#define G3   1536
#define CLN  16      // scan cluster size = grid size (all-to-all DSMEM)

// ---------------- scratch (static device globals; no allocation) ----------------
__device__ float g_visit[(size_t)TT * HD];          // 8 MB
__device__ float g_gi[(size_t)TT * G3];             // 24 MB
__device__ float g_hs[(size_t)TT * HD];             // 8 MB
__device__ float g_logits[TT];
__device__ float g_alpha[TT];
__device__ float g_part[64 * HD];

// ---------------- f32x2 helpers (SASS FFMA2 — PTX-only, ptxas never fuses) ------
__device__ __forceinline__ unsigned long long pk2(float x, float y) {
    unsigned long long r;
    asm("mov.b64 %0, {%1, %2};" : "=l"(r) : "f"(x), "f"(y));
    return r;
}
__device__ __forceinline__ void upk2(unsigned long long p, float& x, float& y) {
    asm("mov.b64 {%0, %1}, %2;" : "=f"(x), "=f"(y) : "l"(p));
}
__device__ __forceinline__ void fma2(unsigned long long& d,
                                     unsigned long long a, unsigned long long b) {
    asm("fma.rn.f32x2 %0, %1, %2, %3;" : "=l"(d) : "l"(a), "l"(b), "l"(d));
}

// ---------------- Phase 1: visit_emb = H^T @ X_emb  (4096x512, K=4880) ----------
__global__ void __launch_bounds__(256) k_visit(const float* __restrict__ H,
                                               const float* __restrict__ X) {
    __shared__ float sA[8][132];   // [k][t]
    __shared__ float sB[8][132];   // [k][v]
    const int tid = threadIdx.x;
    const int t0 = blockIdx.y << 7, v0 = blockIdx.x << 7;
    const int lk = tid >> 5;            // 0..7
    const int lc = (tid & 31) << 2;     // 0..124
    const int ty = tid >> 4;            // 0..15
    const int tx = tid & 15;

    unsigned long long acc2[8][4];
#pragma unroll
    for (int i = 0; i < 8; i++)
#pragma unroll
        for (int jj = 0; jj < 4; jj++) acc2[i][jj] = pk2(0.f, 0.f);

    const float* pa = H + (size_t)lk * TT + t0 + lc;
    const float* pb = X + (size_t)lk * HD + v0 + lc;
    float4 an = *(const float4*)pa;
    float4 bn = *(const float4*)pb;

    for (int c0 = 0; c0 < NC; c0 += 8) {
        *(float4*)&sA[lk][lc] = an;
        *(float4*)&sB[lk][lc] = bn;
        __syncthreads();
        if (c0 + 8 < NC) {
            pa += (size_t)8 * TT;
            pb += (size_t)8 * HD;
            an = *(const float4*)pa;
            bn = *(const float4*)pb;
        }
#pragma unroll
        for (int k = 0; k < 8; k++) {
            float a[8];
            float4 a0 = *(const float4*)&sA[k][ty << 2];
            float4 a1 = *(const float4*)&sA[k][(ty << 2) + 64];
            float4 b0 = *(const float4*)&sB[k][tx << 2];
            float4 b1 = *(const float4*)&sB[k][(tx << 2) + 64];
            a[0]=a0.x; a[1]=a0.y; a[2]=a0.z; a[3]=a0.w;
            a[4]=a1.x; a[5]=a1.y; a[6]=a1.z; a[7]=a1.w;
            unsigned long long bb[4];
            bb[0] = pk2(b0.x, b0.y); bb[1] = pk2(b0.z, b0.w);
            bb[2] = pk2(b1.x, b1.y); bb[3] = pk2(b1.z, b1.w);
#pragma unroll
            for (int i = 0; i < 8; i++) {
                const unsigned long long aa = pk2(a[i], a[i]);
#pragma unroll
                for (int jj = 0; jj < 4; jj++) fma2(acc2[i][jj], aa, bb[jj]);
            }
        }
        __syncthreads();
    }
#pragma unroll
    for (int i = 0; i < 8; i++) {
        int row = t0 + (ty << 2) + (i & 3) + ((i >= 4) ? 64 : 0);
        float4 o0, o1;
        upk2(acc2[i][0], o0.x, o0.y); upk2(acc2[i][1], o0.z, o0.w);
        upk2(acc2[i][2], o1.x, o1.y); upk2(acc2[i][3], o1.z, o1.w);
        *(float4*)&g_visit[(size_t)row * HD + v0 + (tx << 2)]      = o0;
        *(float4*)&g_visit[(size_t)row * HD + v0 + (tx << 2) + 64] = o1;
    }
}

// ---------------- Phase 2: gi = visit_emb @ W_ih^T + b_ih  (4096x1536, K=512) ---
__global__ void __launch_bounds__(256) k_gi(const float* __restrict__ W,
                                            const float* __restrict__ bih) {
    __shared__ float sA[8][132];   // [k][t]
    __shared__ float sB[8][132];   // [k][r]
    const int tid = threadIdx.x;
    const int t0 = blockIdx.y << 7, r0 = blockIdx.x << 7;
    const int lr = tid >> 1;            // 0..127 (row within tile)
    const int lk = (tid & 1) << 2;      // 0 or 4
    const int ty = tid >> 4;            // 0..15
    const int tx = tid & 15;

    unsigned long long acc2[8][4];
#pragma unroll
    for (int i = 0; i < 8; i++)
#pragma unroll
        for (int jj = 0; jj < 4; jj++) acc2[i][jj] = pk2(0.f, 0.f);

    const float* pa = g_visit + (size_t)(t0 + lr) * HD + lk;
    const float* pb = W + (size_t)(r0 + lr) * HD + lk;
    float4 an = *(const float4*)pa;
    float4 bn = *(const float4*)pb;

    for (int k0 = 0; k0 < HD; k0 += 8) {
        sA[lk + 0][lr] = an.x; sA[lk + 1][lr] = an.y;
        sA[lk + 2][lr] = an.z; sA[lk + 3][lr] = an.w;
        sB[lk + 0][lr] = bn.x; sB[lk + 1][lr] = bn.y;
        sB[lk + 2][lr] = bn.z; sB[lk + 3][lr] = bn.w;
        __syncthreads();
        if (k0 + 8 < HD) {
            pa += 8;
            pb += 8;
            an = *(const float4*)pa;
            bn = *(const float4*)pb;
        }
#pragma unroll
        for (int k = 0; k < 8; k++) {
            float a[8];
            float4 a0 = *(const float4*)&sA[k][ty << 2];
            float4 a1 = *(const float4*)&sA[k][(ty << 2) + 64];
            float4 b0 = *(const float4*)&sB[k][tx << 2];
            float4 b1 = *(const float4*)&sB[k][(tx << 2) + 64];
            a[0]=a0.x; a[1]=a0.y; a[2]=a0.z; a[3]=a0.w;
            a[4]=a1.x; a[5]=a1.y; a[6]=a1.z; a[7]=a1.w;
            unsigned long long bb[4];
            bb[0] = pk2(b0.x, b0.y); bb[1] = pk2(b0.z, b0.w);
            bb[2] = pk2(b1.x, b1.y); bb[3] = pk2(b1.z, b1.w);
#pragma unroll
            for (int i = 0; i < 8; i++) {
                const unsigned long long aa = pk2(a[i], a[i]);
#pragma unroll
                for (int jj = 0; jj < 4; jj++) fma2(acc2[i][jj], aa, bb[jj]);
            }
        }
        __syncthreads();
    }
    const float4 bb0 = *(const float4*)&bih[r0 + (tx << 2)];
    const float4 bb1 = *(const float4*)&bih[r0 + (tx << 2) + 64];
#pragma unroll
    for (int i = 0; i < 8; i++) {
        int row = t0 + (ty << 2) + (i & 3) + ((i >= 4) ? 64 : 0);
        float4 o0, o1;
        upk2(acc2[i][0], o0.x, o0.y); upk2(acc2[i][1], o0.z, o0.w);
        upk2(acc2[i][2], o1.x, o1.y); upk2(acc2[i][3], o1.z, o1.w);
        o0.x += bb0.x; o0.y += bb0.y; o0.z += bb0.z; o0.w += bb0.w;
        o1.x += bb1.x; o1.y += bb1.y; o1.z += bb1.z; o1.w += bb1.w;
        *(float4*)&g_gi[(size_t)row * G3 + r0 + (tx << 2)]      = o0;
        *(float4*)&g_gi[(size_t)row * G3 + r0 + (tx << 2) + 64] = o1;
    }
}

// ---------------- Phase 3: GRU scan — cluster-16, mbarrier sync, 256 threads ----
// Grid = cluster = 16 CTAs x 256 threads (8 warps). Warp w of CTA b owns 4
// outputs j0=32b+4w..+3 (all 3 gate rows each = 12 accumulators). Lane l holds
// column pairs {64m+2l, 64m+2l+1}, m=0..7: 96 f32x2 weight regs. 256 thr/CTA
// gives a 256-reg budget -> no spills (512-thr R11 was capped at 128).
// Reduction: 2 xor levels on all 12 accs, keep own gate triple (q = l&3),
// 3 more xor levels on 3 accs (33 SHFL vs 60).
// Sync: per-CTA double-buffered SMEM mbarriers, count=16. After the CTA's
// DSMEM h stores + __syncthreads (cumulativity: all threads' stores happen-
// before), lanes 0-15 do mbarrier.arrive.release.cluster on each rank's
// mbar[nxt]. Consumers try_wait.parity.acquire.cluster on their LOCAL mbar
// (wakeup ~60-90 cyc vs barrier.cluster ~490+). Max skew = 1 step: passing the
// step-t wait requires all 16 CTAs' step-(t-1) arrives, which postdate their
// step-(t-1) reads -> writes into sh[(t+1)&1] can never race a peer's reads
// (same invariant as the R10/R11 cluster barrier). Parity per buffer tracked
// with a flip-after-wait variable (exact, no formula risk).
__global__ void __launch_bounds__(256, 1) __cluster_dims__(CLN, 1, 1)
k_scan(const float* __restrict__ Whh, const float* __restrict__ bhh) {
    const int b = blockIdx.x, tid = threadIdx.x;
    const int w = tid >> 5, l = tid & 31;
    const int q = l & 3;                     // which of the warp's 4 outputs
    const int j0 = (b << 5) + (w << 2);
    const int jo = j0 + q;

    // weights: wv2[rr*8+m] = {Whh[row][64m+2l], Whh[row][64m+2l+1]},
    // rr = gate*4 + out  (gate 0=r,1=z,2=n; out 0..3)
    unsigned long long wv2[96];
#pragma unroll
    for (int rr = 0; rr < 12; rr++) {
        const size_t row = (size_t)(rr >> 2) * HD + j0 + (rr & 3);
#pragma unroll
        for (int m = 0; m < 8; m++) {
            const float2 v = *(const float2*)(Whh + row * HD + (m << 6) + (l << 1));
            wv2[rr * 8 + m] = pk2(v.x, v.y);
        }
    }
    const float br  = bhh[jo];
    const float bz  = bhh[HD + jo];
    const float bnn = bhh[2 * HD + jo];

    __shared__ __align__(16) float sh[2][HD];       // h double buffer
    __shared__ __align__(8) unsigned long long mbar[2];

    const uint32_t mb0 = (uint32_t)__cvta_generic_to_shared(&mbar[0]);
    const uint32_t mb1 = (uint32_t)__cvta_generic_to_shared(&mbar[1]);
    if (tid == 0) {
        asm volatile("mbarrier.init.shared.b64 [%0], %1;" :: "r"(mb0), "r"(16) : "memory");
        asm volatile("mbarrier.init.shared.b64 [%0], %1;" :: "r"(mb1), "r"(16) : "memory");
    }
    for (int i = tid; i < HD; i += 256) sh[0][i] = 0.f;   // h(-1) = 0
    __syncthreads();
    // all CTAs' mbarriers + sh init visible cluster-wide before any remote op
    asm volatile("barrier.cluster.arrive.aligned;" ::: "memory");
    asm volatile("barrier.cluster.wait.aligned;" ::: "memory");

    int par0 = 0, par1 = 0;   // parity per mbarrier, flip after each wait

    for (int t = 0; t < TT; t++) {
        const int p = t & 1;

        // prefetch input-gate values (independent of h; overlaps the wait)
        float ir = 0.f, iz = 0.f, in_ = 0.f;
        if (l < 4) {
            const float* g = g_gi + (size_t)t * G3 + j0 + l;
            ir  = g[0];
            iz  = g[HD];
            in_ = g[2 * HD];
        }

        if (t > 0) {
            const uint32_t mb = p ? mb1 : mb0;
            const int par = p ? par1 : par0;
            unsigned done;
            do {
                asm volatile(
                    "{\n\t"
                    ".reg .pred P;\n\t"
                    "mbarrier.try_wait.parity.acquire.cluster.shared::cta.b64 "
                    "P, [%1], %2, 0x989680;\n\t"
                    "selp.b32 %0, 1, 0, P;\n\t"
                    "}"
                    : "=r"(done) : "r"(mb), "r"(par) : "memory");
            } while (!done);
            if (p) par1 ^= 1; else par0 ^= 1;
        }

        const float* S = sh[p];
        unsigned long long A2[12];
#pragma unroll
        for (int rr = 0; rr < 12; rr++) A2[rr] = pk2(0.f, 0.f);
        const unsigned long long* S2 = (const unsigned long long*)S;
#pragma unroll
        for (int m = 0; m < 8; m++) {
            const unsigned long long hv = S2[(m << 5) + l];
#pragma unroll
            for (int rr = 0; rr < 12; rr++) fma2(A2[rr], wv2[rr * 8 + m], hv);
        }
        float A[12];
#pragma unroll
        for (int rr = 0; rr < 12; rr++) {
            float x, y;
            upk2(A2[rr], x, y);
            A[rr] = x + y;
        }
        // stage 1: sum 4-lane clusters for all 12 accs
#pragma unroll
        for (int rr = 0; rr < 12; rr++) {
            A[rr] += __shfl_xor_sync(0xffffffffu, A[rr], 1);
            A[rr] += __shfl_xor_sync(0xffffffffu, A[rr], 2);
        }
        // stage 2: keep own gate triple, finish over the 8 clusters
        float ar = A[q], az = A[4 + q], an = A[8 + q];
#pragma unroll
        for (int o = 4; o <= 16; o <<= 1) {
            ar += __shfl_xor_sync(0xffffffffu, ar, o);
            az += __shfl_xor_sync(0xffffffffu, az, o);
            an += __shfl_xor_sync(0xffffffffu, an, o);
        }
        // gates: broadcast gi from lanes 0..3, all lanes compute their output
        ir  = __shfl_sync(0xffffffffu, ir,  q);
        iz  = __shfl_sync(0xffffffffu, iz,  q);
        in_ = __shfl_sync(0xffffffffu, in_, q);
        const float r  = 1.f / (1.f + expf(-(ir + ar + br)));
        const float z  = 1.f / (1.f + expf(-(iz + az + bz)));
        const float n  = tanhf(in_ + r * (an + bnn));
        const float hn = (1.f - z) * n + z * S[jo];

        if (l < 4) g_hs[(size_t)t * HD + jo] = hn;

        if (t + 1 < TT) {
            // deliver hn for output jo to two ranks: l>>2 and 8+(l>>2)
            // (lanes with the same q cover ranks 0..7 / 8..15 exactly once)
            const uint32_t laddr =
                (uint32_t)__cvta_generic_to_shared(&sh[p ^ 1][jo]);
            const int r1 = l >> 2;
            asm volatile(
                "{\n\t"
                ".reg .b32 ra;\n\t"
                "mapa.shared::cluster.u32 ra, %0, %1;\n\t"
                "st.shared::cluster.f32 [ra], %2;\n\t"
                "}" :: "r"(laddr), "r"(r1), "f"(hn) : "memory");
            asm volatile(
                "{\n\t"
                ".reg .b32 ra;\n\t"
                "mapa.shared::cluster.u32 ra, %0, %1;\n\t"
                "st.shared::cluster.f32 [ra], %2;\n\t"
                "}" :: "r"(laddr), "r"(r1 + 8), "f"(hn) : "memory");
            __syncthreads();   // all CTA stores happen-before the arrives
            if (tid < 16) {
                const uint32_t mbn = (p ^ 1) ? mb1 : mb0;
                asm volatile(
                    "{\n\t"
                    ".reg .b32 ra;\n\t"
                    "mapa.shared::cluster.u32 ra, %0, %1;\n\t"
                    "mbarrier.arrive.release.cluster.shared::cluster.b64 _, [ra];\n\t"
                    "}" :: "r"(mbn), "r"(tid) : "memory");
            }
        }
    }
    // final step issues no remote ops and its wait consumed all arrivals:
    // safe to exit without a trailing cluster sync
}

// ---------------- Phase 4: attention pooling ------------------------------------
__global__ void k_logits(const float* __restrict__ watt) {
    const int wp = threadIdx.x >> 5, l = threadIdx.x & 31;
    const int t = (blockIdx.x << 3) + wp;
    const float* hr = g_hs + (size_t)t * HD;
    float s = 0.f;
#pragma unroll
    for (int m = 0; m < 16; m++) {
        int k = l + (m << 5);
        s += hr[k] * watt[k];
    }
#pragma unroll
    for (int o = 16; o; o >>= 1) s += __shfl_down_sync(0xffffffffu, s, o);
    if (l == 0) g_logits[t] = s;
}

__global__ void k_softmax() {
    __shared__ float sred[16];
    const int tid = threadIdx.x;   // 512 threads, 8 logits each
    float v[8];
    float mx = -3.402823466e38f;
#pragma unroll
    for (int i = 0; i < 8; i++) {
        v[i] = g_logits[tid + (i << 9)];
        mx = fmaxf(mx, v[i]);
    }
#pragma unroll
    for (int o = 16; o; o >>= 1) mx = fmaxf(mx, __shfl_xor_sync(0xffffffffu, mx, o));
    if ((tid & 31) == 0) sred[tid >> 5] = mx;
    __syncthreads();
    if (tid == 0) {
        float m = sred[0];
        for (int i = 1; i < 16; i++) m = fmaxf(m, sred[i]);
        sred[0] = m;
    }
    __syncthreads();
    const float m = sred[0];
    __syncthreads();
    float s = 0.f;
#pragma unroll
    for (int i = 0; i < 8; i++) {
        v[i] = expf(v[i] - m);
        s += v[i];
    }
#pragma unroll
    for (int o = 16; o; o >>= 1) s += __shfl_xor_sync(0xffffffffu, s, o);
    if ((tid & 31) == 0) sred[tid >> 5] = s;
    __syncthreads();
    if (tid == 0) {
        float S = 0.f;
        for (int i = 0; i < 16; i++) S += sred[i];
        sred[0] = S;
    }
    __syncthreads();
    const float inv = 1.f / sred[0];
#pragma unroll
    for (int i = 0; i < 8; i++) g_alpha[tid + (i << 9)] = v[i] * inv;
}

__global__ void k_wsum() {
    const int j = threadIdx.x, b = blockIdx.x;   // 64 blocks x 512 threads
    float acc = 0.f;
    const int t0 = b << 6;
    for (int t = t0; t < t0 + 64; t++)
        acc += g_alpha[t] * g_hs[(size_t)t * HD + j];
    g_part[b * HD + j] = acc;
}

__global__ void k_final(float* __restrict__ out) {
    const int j = threadIdx.x;
    float a = 0.f;
    for (int b = 0; b < 64; b++) a += g_part[b * HD + j];
    out[j] = a;
}

// ---------------- launch --------------------------------------------------------
extern "C" void kernel_launch(void* const* d_in, const int* in_sizes, int n_in,
                              void* d_out, int out_size) {
    const float* H    = (const float*)d_in[0];
    // d_in[1] = TE (unused by reference)
    const float* X    = (const float*)d_in[2];
    const float* Wih  = (const float*)d_in[3];
    const float* Whh  = (const float*)d_in[4];
    const float* bih  = (const float*)d_in[5];
    const float* bhh  = (const float*)d_in[6];
    const float* watt = (const float*)d_in[7];
    float* out = (float*)d_out;

    // cluster size 16 > portable max 8: opt in (host attr, graph-capture safe)
    cudaFuncSetAttribute((const void*)k_scan,
                         cudaFuncAttributeNonPortableClusterSizeAllowed, 1);

    k_visit<<<dim3(HD / 128, TT / 128), 256>>>(H, X);
    k_gi<<<dim3(G3 / 128, TT / 128), 256>>>(Wih, bih);
    k_scan<<<CLN, 256>>>(Whh, bhh);       // cluster dims from __cluster_dims__
    k_logits<<<TT / 8, 256>>>(watt);
    k_softmax<<<1, 512>>>();
    k_wsum<<<64, 512>>>();
    k_final<<<1, 512>>>(out);
}

// round 13
// speedup vs baseline: 2.5416x; 1.0620x over previous
#include <cuda_runtime.h>
#include <math.h>
#include <stdint.h>

#define TT   4096
#define HD   512
#define NC   4880
#define G3   1536
#define CLN  16      // scan cluster size = grid size (all-to-all DSMEM)

// ---------------- scratch (static device globals; no allocation) ----------------
__device__ float g_visit[(size_t)TT * HD];          // 8 MB
__device__ float g_gi[(size_t)TT * G3];             // 24 MB
__device__ float g_hs[(size_t)TT * HD];             // 8 MB
__device__ float g_logits[TT];
__device__ float g_alpha[TT];
__device__ float g_part[64 * HD];

// ---------------- f32x2 helpers (SASS FFMA2 — PTX-only, ptxas never fuses) ------
__device__ __forceinline__ unsigned long long pk2(float x, float y) {
    unsigned long long r;
    asm("mov.b64 %0, {%1, %2};" : "=l"(r) : "f"(x), "f"(y));
    return r;
}
__device__ __forceinline__ void upk2(unsigned long long p, float& x, float& y) {
    asm("mov.b64 {%0, %1}, %2;" : "=f"(x), "=f"(y) : "l"(p));
}
__device__ __forceinline__ void fma2(unsigned long long& d,
                                     unsigned long long a, unsigned long long b) {
    asm("fma.rn.f32x2 %0, %1, %2, %3;" : "=l"(d) : "l"(a), "l"(b), "l"(d));
}

// ---------------- Phase 1: visit_emb = H^T @ X_emb  (4096x512, K=4880) ----------
__global__ void __launch_bounds__(256) k_visit(const float* __restrict__ H,
                                               const float* __restrict__ X) {
    __shared__ float sA[8][132];   // [k][t]
    __shared__ float sB[8][132];   // [k][v]
    const int tid = threadIdx.x;
    const int t0 = blockIdx.y << 7, v0 = blockIdx.x << 7;
    const int lk = tid >> 5;            // 0..7
    const int lc = (tid & 31) << 2;     // 0..124
    const int ty = tid >> 4;            // 0..15
    const int tx = tid & 15;

    unsigned long long acc2[8][4];
#pragma unroll
    for (int i = 0; i < 8; i++)
#pragma unroll
        for (int jj = 0; jj < 4; jj++) acc2[i][jj] = pk2(0.f, 0.f);

    const float* pa = H + (size_t)lk * TT + t0 + lc;
    const float* pb = X + (size_t)lk * HD + v0 + lc;
    float4 an = *(const float4*)pa;
    float4 bn = *(const float4*)pb;

    for (int c0 = 0; c0 < NC; c0 += 8) {
        *(float4*)&sA[lk][lc] = an;
        *(float4*)&sB[lk][lc] = bn;
        __syncthreads();
        if (c0 + 8 < NC) {
            pa += (size_t)8 * TT;
            pb += (size_t)8 * HD;
            an = *(const float4*)pa;
            bn = *(const float4*)pb;
        }
#pragma unroll
        for (int k = 0; k < 8; k++) {
            float a[8];
            float4 a0 = *(const float4*)&sA[k][ty << 2];
            float4 a1 = *(const float4*)&sA[k][(ty << 2) + 64];
            float4 b0 = *(const float4*)&sB[k][tx << 2];
            float4 b1 = *(const float4*)&sB[k][(tx << 2) + 64];
            a[0]=a0.x; a[1]=a0.y; a[2]=a0.z; a[3]=a0.w;
            a[4]=a1.x; a[5]=a1.y; a[6]=a1.z; a[7]=a1.w;
            unsigned long long bb[4];
            bb[0] = pk2(b0.x, b0.y); bb[1] = pk2(b0.z, b0.w);
            bb[2] = pk2(b1.x, b1.y); bb[3] = pk2(b1.z, b1.w);
#pragma unroll
            for (int i = 0; i < 8; i++) {
                const unsigned long long aa = pk2(a[i], a[i]);
#pragma unroll
                for (int jj = 0; jj < 4; jj++) fma2(acc2[i][jj], aa, bb[jj]);
            }
        }
        __syncthreads();
    }
#pragma unroll
    for (int i = 0; i < 8; i++) {
        int row = t0 + (ty << 2) + (i & 3) + ((i >= 4) ? 64 : 0);
        float4 o0, o1;
        upk2(acc2[i][0], o0.x, o0.y); upk2(acc2[i][1], o0.z, o0.w);
        upk2(acc2[i][2], o1.x, o1.y); upk2(acc2[i][3], o1.z, o1.w);
        *(float4*)&g_visit[(size_t)row * HD + v0 + (tx << 2)]      = o0;
        *(float4*)&g_visit[(size_t)row * HD + v0 + (tx << 2) + 64] = o1;
    }
}

// ---------------- Phase 2: gi = visit_emb @ W_ih^T + b_ih  (4096x1536, K=512) ---
__global__ void __launch_bounds__(256) k_gi(const float* __restrict__ W,
                                            const float* __restrict__ bih) {
    __shared__ float sA[8][132];   // [k][t]
    __shared__ float sB[8][132];   // [k][r]
    const int tid = threadIdx.x;
    const int t0 = blockIdx.y << 7, r0 = blockIdx.x << 7;
    const int lr = tid >> 1;            // 0..127 (row within tile)
    const int lk = (tid & 1) << 2;      // 0 or 4
    const int ty = tid >> 4;            // 0..15
    const int tx = tid & 15;

    unsigned long long acc2[8][4];
#pragma unroll
    for (int i = 0; i < 8; i++)
#pragma unroll
        for (int jj = 0; jj < 4; jj++) acc2[i][jj] = pk2(0.f, 0.f);

    const float* pa = g_visit + (size_t)(t0 + lr) * HD + lk;
    const float* pb = W + (size_t)(r0 + lr) * HD + lk;
    float4 an = *(const float4*)pa;
    float4 bn = *(const float4*)pb;

    for (int k0 = 0; k0 < HD; k0 += 8) {
        sA[lk + 0][lr] = an.x; sA[lk + 1][lr] = an.y;
        sA[lk + 2][lr] = an.z; sA[lk + 3][lr] = an.w;
        sB[lk + 0][lr] = bn.x; sB[lk + 1][lr] = bn.y;
        sB[lk + 2][lr] = bn.z; sB[lk + 3][lr] = bn.w;
        __syncthreads();
        if (k0 + 8 < HD) {
            pa += 8;
            pb += 8;
            an = *(const float4*)pa;
            bn = *(const float4*)pb;
        }
#pragma unroll
        for (int k = 0; k < 8; k++) {
            float a[8];
            float4 a0 = *(const float4*)&sA[k][ty << 2];
            float4 a1 = *(const float4*)&sA[k][(ty << 2) + 64];
            float4 b0 = *(const float4*)&sB[k][tx << 2];
            float4 b1 = *(const float4*)&sB[k][(tx << 2) + 64];
            a[0]=a0.x; a[1]=a0.y; a[2]=a0.z; a[3]=a0.w;
            a[4]=a1.x; a[5]=a1.y; a[6]=a1.z; a[7]=a1.w;
            unsigned long long bb[4];
            bb[0] = pk2(b0.x, b0.y); bb[1] = pk2(b0.z, b0.w);
            bb[2] = pk2(b1.x, b1.y); bb[3] = pk2(b1.z, b1.w);
#pragma unroll
            for (int i = 0; i < 8; i++) {
                const unsigned long long aa = pk2(a[i], a[i]);
#pragma unroll
                for (int jj = 0; jj < 4; jj++) fma2(acc2[i][jj], aa, bb[jj]);
            }
        }
        __syncthreads();
    }
    const float4 bb0 = *(const float4*)&bih[r0 + (tx << 2)];
    const float4 bb1 = *(const float4*)&bih[r0 + (tx << 2) + 64];
#pragma unroll
    for (int i = 0; i < 8; i++) {
        int row = t0 + (ty << 2) + (i & 3) + ((i >= 4) ? 64 : 0);
        float4 o0, o1;
        upk2(acc2[i][0], o0.x, o0.y); upk2(acc2[i][1], o0.z, o0.w);
        upk2(acc2[i][2], o1.x, o1.y); upk2(acc2[i][3], o1.z, o1.w);
        o0.x += bb0.x; o0.y += bb0.y; o0.z += bb0.z; o0.w += bb0.w;
        o1.x += bb1.x; o1.y += bb1.y; o1.z += bb1.z; o1.w += bb1.w;
        *(float4*)&g_gi[(size_t)row * G3 + r0 + (tx << 2)]      = o0;
        *(float4*)&g_gi[(size_t)row * G3 + r0 + (tx << 2) + 64] = o1;
    }
}

// ---------------- Phase 3: GRU scan — cluster-16, mbarrier sync, 256 threads ----
// Same structure as R12 (proven). Changes this round:
//  (1) gates via tanh-only forms: sigmoid(x) = 0.5 + 0.5*tanh(x/2) — removes two
//      div.rn.f32 + one libm exp from the per-step serial latency chain; libm
//      tanhf keeps 1-2 ulp accuracy (the R3/R5 failures were approx intrinsics,
//      not reordering).
//  (2) DSMEM delivery packed as f32x2: even-q lanes shfl the neighbor's hn and
//      issue ONE st.shared::cluster.b64 per rank — halves remote transactions
//      on the 17 B/cyc producer-pays smem port.
__global__ void __launch_bounds__(256, 1) __cluster_dims__(CLN, 1, 1)
k_scan(const float* __restrict__ Whh, const float* __restrict__ bhh) {
    const int b = blockIdx.x, tid = threadIdx.x;
    const int w = tid >> 5, l = tid & 31;
    const int q = l & 3;                     // which of the warp's 4 outputs
    const int j0 = (b << 5) + (w << 2);
    const int jo = j0 + q;

    // weights: wv2[rr*8+m] = {Whh[row][64m+2l], Whh[row][64m+2l+1]},
    // rr = gate*4 + out  (gate 0=r,1=z,2=n; out 0..3)
    unsigned long long wv2[96];
#pragma unroll
    for (int rr = 0; rr < 12; rr++) {
        const size_t row = (size_t)(rr >> 2) * HD + j0 + (rr & 3);
#pragma unroll
        for (int m = 0; m < 8; m++) {
            const float2 v = *(const float2*)(Whh + row * HD + (m << 6) + (l << 1));
            wv2[rr * 8 + m] = pk2(v.x, v.y);
        }
    }
    const float br  = bhh[jo];
    const float bz  = bhh[HD + jo];
    const float bnn = bhh[2 * HD + jo];

    __shared__ __align__(16) float sh[2][HD];       // h double buffer
    __shared__ __align__(8) unsigned long long mbar[2];

    const uint32_t mb0 = (uint32_t)__cvta_generic_to_shared(&mbar[0]);
    const uint32_t mb1 = (uint32_t)__cvta_generic_to_shared(&mbar[1]);
    if (tid == 0) {
        asm volatile("mbarrier.init.shared.b64 [%0], %1;" :: "r"(mb0), "r"(16) : "memory");
        asm volatile("mbarrier.init.shared.b64 [%0], %1;" :: "r"(mb1), "r"(16) : "memory");
    }
    for (int i = tid; i < HD; i += 256) sh[0][i] = 0.f;   // h(-1) = 0
    __syncthreads();
    // all CTAs' mbarriers + sh init visible cluster-wide before any remote op
    asm volatile("barrier.cluster.arrive.aligned;" ::: "memory");
    asm volatile("barrier.cluster.wait.aligned;" ::: "memory");

    int par0 = 0, par1 = 0;   // parity per mbarrier, flip after each wait

    for (int t = 0; t < TT; t++) {
        const int p = t & 1;

        // prefetch input-gate values (independent of h; overlaps the wait)
        float ir = 0.f, iz = 0.f, in_ = 0.f;
        if (l < 4) {
            const float* g = g_gi + (size_t)t * G3 + j0 + l;
            ir  = g[0];
            iz  = g[HD];
            in_ = g[2 * HD];
        }

        if (t > 0) {
            const uint32_t mb = p ? mb1 : mb0;
            const int par = p ? par1 : par0;
            unsigned done;
            do {
                asm volatile(
                    "{\n\t"
                    ".reg .pred P;\n\t"
                    "mbarrier.try_wait.parity.acquire.cluster.shared::cta.b64 "
                    "P, [%1], %2, 0x989680;\n\t"
                    "selp.b32 %0, 1, 0, P;\n\t"
                    "}"
                    : "=r"(done) : "r"(mb), "r"(par) : "memory");
            } while (!done);
            if (p) par1 ^= 1; else par0 ^= 1;
        }

        const float* S = sh[p];
        unsigned long long A2[12];
#pragma unroll
        for (int rr = 0; rr < 12; rr++) A2[rr] = pk2(0.f, 0.f);
        const unsigned long long* S2 = (const unsigned long long*)S;
#pragma unroll
        for (int m = 0; m < 8; m++) {
            const unsigned long long hv = S2[(m << 5) + l];
#pragma unroll
            for (int rr = 0; rr < 12; rr++) fma2(A2[rr], wv2[rr * 8 + m], hv);
        }
        float A[12];
#pragma unroll
        for (int rr = 0; rr < 12; rr++) {
            float x, y;
            upk2(A2[rr], x, y);
            A[rr] = x + y;
        }
        // stage 1: sum 4-lane clusters for all 12 accs
#pragma unroll
        for (int rr = 0; rr < 12; rr++) {
            A[rr] += __shfl_xor_sync(0xffffffffu, A[rr], 1);
            A[rr] += __shfl_xor_sync(0xffffffffu, A[rr], 2);
        }
        // stage 2: keep own gate triple, finish over the 8 clusters
        float ar = A[q], az = A[4 + q], an = A[8 + q];
#pragma unroll
        for (int o = 4; o <= 16; o <<= 1) {
            ar += __shfl_xor_sync(0xffffffffu, ar, o);
            az += __shfl_xor_sync(0xffffffffu, az, o);
            an += __shfl_xor_sync(0xffffffffu, an, o);
        }
        // gates: broadcast gi from lanes 0..3, all lanes compute their output.
        // sigmoid(x) = 0.5 + 0.5*tanh(0.5x) — identical math, no div.rn, one
        // libm call per gate instead of exp+div.
        ir  = __shfl_sync(0xffffffffu, ir,  q);
        iz  = __shfl_sync(0xffffffffu, iz,  q);
        in_ = __shfl_sync(0xffffffffu, in_, q);
        const float r  = 0.5f + 0.5f * tanhf(0.5f * (ir + ar + br));
        const float z  = 0.5f + 0.5f * tanhf(0.5f * (iz + az + bz));
        const float n  = tanhf(in_ + r * (an + bnn));
        const float hn = (1.f - z) * n + z * S[jo];

        if (l < 4) g_hs[(size_t)t * HD + jo] = hn;

        // pack neighbor's hn: even-q lanes hold {hn(jo), hn(jo+1)}
        const float hn_hi = __shfl_down_sync(0xffffffffu, hn, 1);

        if (t + 1 < TT) {
            if (!(q & 1)) {
                // deliver the pair {jo, jo+1} (jo even -> 8B aligned) to two
                // ranks: l>>2 and 8+(l>>2). Even-q lanes with the same q cover
                // ranks 0..7 / 8..15 exactly once per pair.
                const unsigned long long pv = pk2(hn, hn_hi);
                const uint32_t laddr =
                    (uint32_t)__cvta_generic_to_shared(&sh[p ^ 1][jo]);
                const int r1 = l >> 2;
                asm volatile(
                    "{\n\t"
                    ".reg .b32 ra;\n\t"
                    "mapa.shared::cluster.u32 ra, %0, %1;\n\t"
                    "st.shared::cluster.b64 [ra], %2;\n\t"
                    "}" :: "r"(laddr), "r"(r1), "l"(pv) : "memory");
                asm volatile(
                    "{\n\t"
                    ".reg .b32 ra;\n\t"
                    "mapa.shared::cluster.u32 ra, %0, %1;\n\t"
                    "st.shared::cluster.b64 [ra], %2;\n\t"
                    "}" :: "r"(laddr), "r"(r1 + 8), "l"(pv) : "memory");
            }
            __syncthreads();   // all CTA stores happen-before the arrives
            if (tid < 16) {
                const uint32_t mbn = (p ^ 1) ? mb1 : mb0;
                asm volatile(
                    "{\n\t"
                    ".reg .b32 ra;\n\t"
                    "mapa.shared::cluster.u32 ra, %0, %1;\n\t"
                    "mbarrier.arrive.release.cluster.shared::cluster.b64 _, [ra];\n\t"
                    "}" :: "r"(mbn), "r"(tid) : "memory");
            }
        }
    }
}

// ---------------- Phase 4: attention pooling ------------------------------------
__global__ void k_logits(const float* __restrict__ watt) {
    const int wp = threadIdx.x >> 5, l = threadIdx.x & 31;
    const int t = (blockIdx.x << 3) + wp;
    const float* hr = g_hs + (size_t)t * HD;
    float s = 0.f;
#pragma unroll
    for (int m = 0; m < 16; m++) {
        int k = l + (m << 5);
        s += hr[k] * watt[k];
    }
#pragma unroll
    for (int o = 16; o; o >>= 1) s += __shfl_down_sync(0xffffffffu, s, o);
    if (l == 0) g_logits[t] = s;
}

__global__ void k_softmax() {
    __shared__ float sred[16];
    const int tid = threadIdx.x;   // 512 threads, 8 logits each
    float v[8];
    float mx = -3.402823466e38f;
#pragma unroll
    for (int i = 0; i < 8; i++) {
        v[i] = g_logits[tid + (i << 9)];
        mx = fmaxf(mx, v[i]);
    }
#pragma unroll
    for (int o = 16; o; o >>= 1) mx = fmaxf(mx, __shfl_xor_sync(0xffffffffu, mx, o));
    if ((tid & 31) == 0) sred[tid >> 5] = mx;
    __syncthreads();
    if (tid == 0) {
        float m = sred[0];
        for (int i = 1; i < 16; i++) m = fmaxf(m, sred[i]);
        sred[0] = m;
    }
    __syncthreads();
    const float m = sred[0];
    __syncthreads();
    float s = 0.f;
#pragma unroll
    for (int i = 0; i < 8; i++) {
        v[i] = expf(v[i] - m);
        s += v[i];
    }
#pragma unroll
    for (int o = 16; o; o >>= 1) s += __shfl_xor_sync(0xffffffffu, s, o);
    if ((tid & 31) == 0) sred[tid >> 5] = s;
    __syncthreads();
    if (tid == 0) {
        float S = 0.f;
        for (int i = 0; i < 16; i++) S += sred[i];
        sred[0] = S;
    }
    __syncthreads();
    const float inv = 1.f / sred[0];
#pragma unroll
    for (int i = 0; i < 8; i++) g_alpha[tid + (i << 9)] = v[i] * inv;
}

__global__ void k_wsum() {
    const int j = threadIdx.x, b = blockIdx.x;   // 64 blocks x 512 threads
    float acc = 0.f;
    const int t0 = b << 6;
    for (int t = t0; t < t0 + 64; t++)
        acc += g_alpha[t] * g_hs[(size_t)t * HD + j];
    g_part[b * HD + j] = acc;
}

__global__ void k_final(float* __restrict__ out) {
    const int j = threadIdx.x;
    float a = 0.f;
    for (int b = 0; b < 64; b++) a += g_part[b * HD + j];
    out[j] = a;
}

// ---------------- launch --------------------------------------------------------
extern "C" void kernel_launch(void* const* d_in, const int* in_sizes, int n_in,
                              void* d_out, int out_size) {
    const float* H    = (const float*)d_in[0];
    // d_in[1] = TE (unused by reference)
    const float* X    = (const float*)d_in[2];
    const float* Wih  = (const float*)d_in[3];
    const float* Whh  = (const float*)d_in[4];
    const float* bih  = (const float*)d_in[5];
    const float* bhh  = (const float*)d_in[6];
    const float* watt = (const float*)d_in[7];
    float* out = (float*)d_out;

    // cluster size 16 > portable max 8: opt in (host attr, graph-capture safe)
    cudaFuncSetAttribute((const void*)k_scan,
                         cudaFuncAttributeNonPortableClusterSizeAllowed, 1);

    k_visit<<<dim3(HD / 128, TT / 128), 256>>>(H, X);
    k_gi<<<dim3(G3 / 128, TT / 128), 256>>>(Wih, bih);
    k_scan<<<CLN, 256>>>(Whh, bhh);       // cluster dims from __cluster_dims__
    k_logits<<<TT / 8, 256>>>(watt);
    k_softmax<<<1, 512>>>();
    k_wsum<<<64, 512>>>();
    k_final<<<1, 512>>>(out);
}

// round 14
// speedup vs baseline: 3.5571x; 1.3995x over previous
#include <cuda_runtime.h>
#include <math.h>
#include <stdint.h>

#define TT   4096
#define HD   512
#define NC   4880
#define G3   1536
#define CLN  16      // scan cluster size = grid size (all-to-all DSMEM)

// ---------------- scratch (static device globals; no allocation) ----------------
__device__ float g_visit[(size_t)TT * HD];          // 8 MB
__device__ float g_gi[(size_t)TT * G3];             // 24 MB
__device__ float g_hs[(size_t)TT * HD];             // 8 MB
__device__ float g_logits[TT];
__device__ float g_alpha[TT];
__device__ float g_part[64 * HD];

// ---------------- f32x2 helpers (SASS FFMA2 — PTX-only, ptxas never fuses) ------
__device__ __forceinline__ unsigned long long pk2(float x, float y) {
    unsigned long long r;
    asm("mov.b64 %0, {%1, %2};" : "=l"(r) : "f"(x), "f"(y));
    return r;
}
__device__ __forceinline__ void upk2(unsigned long long p, float& x, float& y) {
    asm("mov.b64 {%0, %1}, %2;" : "=f"(x), "=f"(y) : "l"(p));
}
__device__ __forceinline__ void fma2(unsigned long long& d,
                                     unsigned long long a, unsigned long long b) {
    asm("fma.rn.f32x2 %0, %1, %2, %3;" : "=l"(d) : "l"(a), "l"(b), "l"(d));
}

// ---------------- Phase 1: visit_emb = H^T @ X_emb  (4096x512, K=4880) ----------
__global__ void __launch_bounds__(256) k_visit(const float* __restrict__ H,
                                               const float* __restrict__ X) {
    __shared__ float sA[8][132];   // [k][t]
    __shared__ float sB[8][132];   // [k][v]
    const int tid = threadIdx.x;
    const int t0 = blockIdx.y << 7, v0 = blockIdx.x << 7;
    const int lk = tid >> 5;            // 0..7
    const int lc = (tid & 31) << 2;     // 0..124
    const int ty = tid >> 4;            // 0..15
    const int tx = tid & 15;

    unsigned long long acc2[8][4];
#pragma unroll
    for (int i = 0; i < 8; i++)
#pragma unroll
        for (int jj = 0; jj < 4; jj++) acc2[i][jj] = pk2(0.f, 0.f);

    const float* pa = H + (size_t)lk * TT + t0 + lc;
    const float* pb = X + (size_t)lk * HD + v0 + lc;
    float4 an = *(const float4*)pa;
    float4 bn = *(const float4*)pb;

    for (int c0 = 0; c0 < NC; c0 += 8) {
        *(float4*)&sA[lk][lc] = an;
        *(float4*)&sB[lk][lc] = bn;
        __syncthreads();
        if (c0 + 8 < NC) {
            pa += (size_t)8 * TT;
            pb += (size_t)8 * HD;
            an = *(const float4*)pa;
            bn = *(const float4*)pb;
        }
#pragma unroll
        for (int k = 0; k < 8; k++) {
            float a[8];
            float4 a0 = *(const float4*)&sA[k][ty << 2];
            float4 a1 = *(const float4*)&sA[k][(ty << 2) + 64];
            float4 b0 = *(const float4*)&sB[k][tx << 2];
            float4 b1 = *(const float4*)&sB[k][(tx << 2) + 64];
            a[0]=a0.x; a[1]=a0.y; a[2]=a0.z; a[3]=a0.w;
            a[4]=a1.x; a[5]=a1.y; a[6]=a1.z; a[7]=a1.w;
            unsigned long long bb[4];
            bb[0] = pk2(b0.x, b0.y); bb[1] = pk2(b0.z, b0.w);
            bb[2] = pk2(b1.x, b1.y); bb[3] = pk2(b1.z, b1.w);
#pragma unroll
            for (int i = 0; i < 8; i++) {
                const unsigned long long aa = pk2(a[i], a[i]);
#pragma unroll
                for (int jj = 0; jj < 4; jj++) fma2(acc2[i][jj], aa, bb[jj]);
            }
        }
        __syncthreads();
    }
#pragma unroll
    for (int i = 0; i < 8; i++) {
        int row = t0 + (ty << 2) + (i & 3) + ((i >= 4) ? 64 : 0);
        float4 o0, o1;
        upk2(acc2[i][0], o0.x, o0.y); upk2(acc2[i][1], o0.z, o0.w);
        upk2(acc2[i][2], o1.x, o1.y); upk2(acc2[i][3], o1.z, o1.w);
        *(float4*)&g_visit[(size_t)row * HD + v0 + (tx << 2)]      = o0;
        *(float4*)&g_visit[(size_t)row * HD + v0 + (tx << 2) + 64] = o1;
    }
}

// ---------------- Phase 2: gi = visit_emb @ W_ih^T + b_ih  (4096x1536, K=512) ---
__global__ void __launch_bounds__(256) k_gi(const float* __restrict__ W,
                                            const float* __restrict__ bih) {
    __shared__ float sA[8][132];   // [k][t]
    __shared__ float sB[8][132];   // [k][r]
    const int tid = threadIdx.x;
    const int t0 = blockIdx.y << 7, r0 = blockIdx.x << 7;
    const int lr = tid >> 1;            // 0..127 (row within tile)
    const int lk = (tid & 1) << 2;      // 0 or 4
    const int ty = tid >> 4;            // 0..15
    const int tx = tid & 15;

    unsigned long long acc2[8][4];
#pragma unroll
    for (int i = 0; i < 8; i++)
#pragma unroll
        for (int jj = 0; jj < 4; jj++) acc2[i][jj] = pk2(0.f, 0.f);

    const float* pa = g_visit + (size_t)(t0 + lr) * HD + lk;
    const float* pb = W + (size_t)(r0 + lr) * HD + lk;
    float4 an = *(const float4*)pa;
    float4 bn = *(const float4*)pb;

    for (int k0 = 0; k0 < HD; k0 += 8) {
        sA[lk + 0][lr] = an.x; sA[lk + 1][lr] = an.y;
        sA[lk + 2][lr] = an.z; sA[lk + 3][lr] = an.w;
        sB[lk + 0][lr] = bn.x; sB[lk + 1][lr] = bn.y;
        sB[lk + 2][lr] = bn.z; sB[lk + 3][lr] = bn.w;
        __syncthreads();
        if (k0 + 8 < HD) {
            pa += 8;
            pb += 8;
            an = *(const float4*)pa;
            bn = *(const float4*)pb;
        }
#pragma unroll
        for (int k = 0; k < 8; k++) {
            float a[8];
            float4 a0 = *(const float4*)&sA[k][ty << 2];
            float4 a1 = *(const float4*)&sA[k][(ty << 2) + 64];
            float4 b0 = *(const float4*)&sB[k][tx << 2];
            float4 b1 = *(const float4*)&sB[k][(tx << 2) + 64];
            a[0]=a0.x; a[1]=a0.y; a[2]=a0.z; a[3]=a0.w;
            a[4]=a1.x; a[5]=a1.y; a[6]=a1.z; a[7]=a1.w;
            unsigned long long bb[4];
            bb[0] = pk2(b0.x, b0.y); bb[1] = pk2(b0.z, b0.w);
            bb[2] = pk2(b1.x, b1.y); bb[3] = pk2(b1.z, b1.w);
#pragma unroll
            for (int i = 0; i < 8; i++) {
                const unsigned long long aa = pk2(a[i], a[i]);
#pragma unroll
                for (int jj = 0; jj < 4; jj++) fma2(acc2[i][jj], aa, bb[jj]);
            }
        }
        __syncthreads();
    }
    const float4 bb0 = *(const float4*)&bih[r0 + (tx << 2)];
    const float4 bb1 = *(const float4*)&bih[r0 + (tx << 2) + 64];
#pragma unroll
    for (int i = 0; i < 8; i++) {
        int row = t0 + (ty << 2) + (i & 3) + ((i >= 4) ? 64 : 0);
        float4 o0, o1;
        upk2(acc2[i][0], o0.x, o0.y); upk2(acc2[i][1], o0.z, o0.w);
        upk2(acc2[i][2], o1.x, o1.y); upk2(acc2[i][3], o1.z, o1.w);
        o0.x += bb0.x; o0.y += bb0.y; o0.z += bb0.z; o0.w += bb0.w;
        o1.x += bb1.x; o1.y += bb1.y; o1.z += bb1.z; o1.w += bb1.w;
        *(float4*)&g_gi[(size_t)row * G3 + r0 + (tx << 2)]      = o0;
        *(float4*)&g_gi[(size_t)row * G3 + r0 + (tx << 2) + 64] = o1;
    }
}

// ---------------- Phase 3: GRU scan — cluster-16, st.async fused delivery -------
// Same compute structure as R13 (proven). Delivery change: each warp packs its
// 4 outputs into 16B (3 shfl_down); q==0 lanes issue ONE
// st.async.mbarrier::complete_tx::bytes.v2.b64 to each of 2 ranks — the store
// ITSELF signals the remote mbarrier (tx-based), fusing the R13 two-hop
// {store -> __syncthreads -> arrive.release} chain into one fabric hop with no
// block barrier. Each CTA's mbar[buf] is armed with arrive.expect_tx(2048)
// (= 16 CTAs x 8 warps x 16B) once per phase: at init for steps 1/2, then
// re-armed by thread 0 right after each wait (for step t+2). Causally safe:
// a peer's step-(t+2) sends require its step-(t+1) wait, which requires MY
// step-(t+1) 2048B including warp-0's stores, which follow thread-0's re-arm
// in program order. Phase completion proves every peer warp's matvec reads of
// the previous buffer finished (each warp reads all 512 slots; its packed
// store data-depends on those reads) -> the 1-step-skew double-buffer WAR
// invariant of R12/R13 carries over verbatim.
__global__ void __launch_bounds__(256, 1) __cluster_dims__(CLN, 1, 1)
k_scan(const float* __restrict__ Whh, const float* __restrict__ bhh) {
    const int b = blockIdx.x, tid = threadIdx.x;
    const int w = tid >> 5, l = tid & 31;
    const int q = l & 3;                     // which of the warp's 4 outputs
    const int j0 = (b << 5) + (w << 2);
    const int jo = j0 + q;

    // weights: wv2[rr*8+m] = {Whh[row][64m+2l], Whh[row][64m+2l+1]},
    // rr = gate*4 + out  (gate 0=r,1=z,2=n; out 0..3)
    unsigned long long wv2[96];
#pragma unroll
    for (int rr = 0; rr < 12; rr++) {
        const size_t row = (size_t)(rr >> 2) * HD + j0 + (rr & 3);
#pragma unroll
        for (int m = 0; m < 8; m++) {
            const float2 v = *(const float2*)(Whh + row * HD + (m << 6) + (l << 1));
            wv2[rr * 8 + m] = pk2(v.x, v.y);
        }
    }
    const float br  = bhh[jo];
    const float bz  = bhh[HD + jo];
    const float bnn = bhh[2 * HD + jo];

    __shared__ __align__(16) float sh[2][HD];       // h double buffer
    __shared__ __align__(8) unsigned long long mbar[2];

    const uint32_t mb0 = (uint32_t)__cvta_generic_to_shared(&mbar[0]);
    const uint32_t mb1 = (uint32_t)__cvta_generic_to_shared(&mbar[1]);
    if (tid == 0) {
        asm volatile("mbarrier.init.shared.b64 [%0], %1;" :: "r"(mb0), "r"(1) : "memory");
        asm volatile("mbarrier.init.shared.b64 [%0], %1;" :: "r"(mb1), "r"(1) : "memory");
        // arm: mbar[1] completes for step 1, mbar[0] for step 2 (2048B each)
        asm volatile("mbarrier.arrive.expect_tx.shared.b64 _, [%0], %1;"
                     :: "r"(mb1), "r"(2048u) : "memory");
        asm volatile("mbarrier.arrive.expect_tx.shared.b64 _, [%0], %1;"
                     :: "r"(mb0), "r"(2048u) : "memory");
    }
    for (int i = tid; i < HD; i += 256) sh[0][i] = 0.f;   // h(-1) = 0
    __syncthreads();
    // all CTAs' mbarriers init+armed visible cluster-wide before any st.async
    asm volatile("barrier.cluster.arrive.aligned;" ::: "memory");
    asm volatile("barrier.cluster.wait.aligned;" ::: "memory");

    int par0 = 0, par1 = 0;   // parity per mbarrier, flip after each wait

    for (int t = 0; t < TT; t++) {
        const int p = t & 1;

        // prefetch input-gate values (independent of h; overlaps the wait)
        float ir = 0.f, iz = 0.f, in_ = 0.f;
        if (l < 4) {
            const float* g = g_gi + (size_t)t * G3 + j0 + l;
            ir  = g[0];
            iz  = g[HD];
            in_ = g[2 * HD];
        }

        if (t > 0) {
            const uint32_t mb = p ? mb1 : mb0;
            const int par = p ? par1 : par0;
            unsigned done;
            do {
                asm volatile(
                    "{\n\t"
                    ".reg .pred P;\n\t"
                    "mbarrier.try_wait.parity.acquire.cluster.shared::cta.b64 "
                    "P, [%1], %2, 0x989680;\n\t"
                    "selp.b32 %0, 1, 0, P;\n\t"
                    "}"
                    : "=r"(done) : "r"(mb), "r"(par) : "memory");
            } while (!done);
            if (p) par1 ^= 1; else par0 ^= 1;
            // re-arm this mbarrier for its next phase (step t+2)
            if (tid == 0)
                asm volatile("mbarrier.arrive.expect_tx.shared.b64 _, [%0], %1;"
                             :: "r"(mb), "r"(2048u) : "memory");
        }

        const float* S = sh[p];
        unsigned long long A2[12];
#pragma unroll
        for (int rr = 0; rr < 12; rr++) A2[rr] = pk2(0.f, 0.f);
        const unsigned long long* S2 = (const unsigned long long*)S;
#pragma unroll
        for (int m = 0; m < 8; m++) {
            const unsigned long long hv = S2[(m << 5) + l];
#pragma unroll
            for (int rr = 0; rr < 12; rr++) fma2(A2[rr], wv2[rr * 8 + m], hv);
        }
        float A[12];
#pragma unroll
        for (int rr = 0; rr < 12; rr++) {
            float x, y;
            upk2(A2[rr], x, y);
            A[rr] = x + y;
        }
        // stage 1: sum 4-lane clusters for all 12 accs
#pragma unroll
        for (int rr = 0; rr < 12; rr++) {
            A[rr] += __shfl_xor_sync(0xffffffffu, A[rr], 1);
            A[rr] += __shfl_xor_sync(0xffffffffu, A[rr], 2);
        }
        // stage 2: keep own gate triple, finish over the 8 clusters
        float ar = A[q], az = A[4 + q], an = A[8 + q];
#pragma unroll
        for (int o = 4; o <= 16; o <<= 1) {
            ar += __shfl_xor_sync(0xffffffffu, ar, o);
            az += __shfl_xor_sync(0xffffffffu, az, o);
            an += __shfl_xor_sync(0xffffffffu, an, o);
        }
        // gates: sigmoid(x) = 0.5 + 0.5*tanh(0.5x) (identical math, no div.rn)
        ir  = __shfl_sync(0xffffffffu, ir,  q);
        iz  = __shfl_sync(0xffffffffu, iz,  q);
        in_ = __shfl_sync(0xffffffffu, in_, q);
        const float r  = 0.5f + 0.5f * tanhf(0.5f * (ir + ar + br));
        const float z  = 0.5f + 0.5f * tanhf(0.5f * (iz + az + bz));
        const float n  = tanhf(in_ + r * (an + bnn));
        const float hn = (1.f - z) * n + z * S[jo];

        if (l < 4) g_hs[(size_t)t * HD + jo] = hn;

        if (t + 1 < TT) {
            // pack the warp's 4 outputs onto its q==0 lanes (h(j0..j0+3))
            const float h1 = __shfl_down_sync(0xffffffffu, hn, 1);
            const float h2 = __shfl_down_sync(0xffffffffu, hn, 2);
            const float h3 = __shfl_down_sync(0xffffffffu, hn, 3);
            if (q == 0) {
                const unsigned long long v0 = pk2(hn, h1);
                const unsigned long long v1 = pk2(h2, h3);
                const uint32_t laddr =
                    (uint32_t)__cvta_generic_to_shared(&sh[p ^ 1][j0]);
                const uint32_t mbn = (p ^ 1) ? mb1 : mb0;
                const int r1 = l >> 2;      // q0 lanes: l=0,4..28 -> r1=0..7
                // one fused store+signal per rank (r1 and r1+8)
                asm volatile(
                    "{\n\t"
                    ".reg .b32 ra, rb;\n\t"
                    "mapa.shared::cluster.u32 ra, %0, %1;\n\t"
                    "mapa.shared::cluster.u32 rb, %2, %1;\n\t"
                    "st.async.weak.shared::cluster.mbarrier::complete_tx::bytes"
                    ".v2.b64 [ra], {%3, %4}, [rb];\n\t"
                    "}" :: "r"(laddr), "r"(r1), "r"(mbn),
                           "l"(v0), "l"(v1) : "memory");
                asm volatile(
                    "{\n\t"
                    ".reg .b32 ra, rb;\n\t"
                    "mapa.shared::cluster.u32 ra, %0, %1;\n\t"
                    "mapa.shared::cluster.u32 rb, %2, %1;\n\t"
                    "st.async.weak.shared::cluster.mbarrier::complete_tx::bytes"
                    ".v2.b64 [ra], {%3, %4}, [rb];\n\t"
                    "}" :: "r"(laddr), "r"(r1 + 8), "r"(mbn),
                           "l"(v0), "l"(v1) : "memory");
            }
        }
    }
}

// ---------------- Phase 4: attention pooling ------------------------------------
__global__ void k_logits(const float* __restrict__ watt) {
    const int wp = threadIdx.x >> 5, l = threadIdx.x & 31;
    const int t = (blockIdx.x << 3) + wp;
    const float* hr = g_hs + (size_t)t * HD;
    float s = 0.f;
#pragma unroll
    for (int m = 0; m < 16; m++) {
        int k = l + (m << 5);
        s += hr[k] * watt[k];
    }
#pragma unroll
    for (int o = 16; o; o >>= 1) s += __shfl_down_sync(0xffffffffu, s, o);
    if (l == 0) g_logits[t] = s;
}

__global__ void k_softmax() {
    __shared__ float sred[16];
    const int tid = threadIdx.x;   // 512 threads, 8 logits each
    float v[8];
    float mx = -3.402823466e38f;
#pragma unroll
    for (int i = 0; i < 8; i++) {
        v[i] = g_logits[tid + (i << 9)];
        mx = fmaxf(mx, v[i]);
    }
#pragma unroll
    for (int o = 16; o; o >>= 1) mx = fmaxf(mx, __shfl_xor_sync(0xffffffffu, mx, o));
    if ((tid & 31) == 0) sred[tid >> 5] = mx;
    __syncthreads();
    if (tid == 0) {
        float m = sred[0];
        for (int i = 1; i < 16; i++) m = fmaxf(m, sred[i]);
        sred[0] = m;
    }
    __syncthreads();
    const float m = sred[0];
    __syncthreads();
    float s = 0.f;
#pragma unroll
    for (int i = 0; i < 8; i++) {
        v[i] = expf(v[i] - m);
        s += v[i];
    }
#pragma unroll
    for (int o = 16; o; o >>= 1) s += __shfl_xor_sync(0xffffffffu, s, o);
    if ((tid & 31) == 0) sred[tid >> 5] = s;
    __syncthreads();
    if (tid == 0) {
        float S = 0.f;
        for (int i = 0; i < 16; i++) S += sred[i];
        sred[0] = S;
    }
    __syncthreads();
    const float inv = 1.f / sred[0];
#pragma unroll
    for (int i = 0; i < 8; i++) g_alpha[tid + (i << 9)] = v[i] * inv;
}

__global__ void k_wsum() {
    const int j = threadIdx.x, b = blockIdx.x;   // 64 blocks x 512 threads
    float acc = 0.f;
    const int t0 = b << 6;
    for (int t = t0; t < t0 + 64; t++)
        acc += g_alpha[t] * g_hs[(size_t)t * HD + j];
    g_part[b * HD + j] = acc;
}

__global__ void k_final(float* __restrict__ out) {
    const int j = threadIdx.x;
    float a = 0.f;
    for (int b = 0; b < 64; b++) a += g_part[b * HD + j];
    out[j] = a;
}

// ---------------- launch --------------------------------------------------------
extern "C" void kernel_launch(void* const* d_in, const int* in_sizes, int n_in,
                              void* d_out, int out_size) {
    const float* H    = (const float*)d_in[0];
    // d_in[1] = TE (unused by reference)
    const float* X    = (const float*)d_in[2];
    const float* Wih  = (const float*)d_in[3];
    const float* Whh  = (const float*)d_in[4];
    const float* bih  = (const float*)d_in[5];
    const float* bhh  = (const float*)d_in[6];
    const float* watt = (const float*)d_in[7];
    float* out = (float*)d_out;

    // cluster size 16 > portable max 8: opt in (host attr, graph-capture safe)
    cudaFuncSetAttribute((const void*)k_scan,
                         cudaFuncAttributeNonPortableClusterSizeAllowed, 1);

    k_visit<<<dim3(HD / 128, TT / 128), 256>>>(H, X);
    k_gi<<<dim3(G3 / 128, TT / 128), 256>>>(Wih, bih);
    k_scan<<<CLN, 256>>>(Whh, bhh);       // cluster dims from __cluster_dims__
    k_logits<<<TT / 8, 256>>>(watt);
    k_softmax<<<1, 512>>>();
    k_wsum<<<64, 512>>>();
    k_final<<<1, 512>>>(out);
}